// round 12
// baseline (speedup 1.0000x reference)
#include <cuda_runtime.h>
#include <cuda_bf16.h>
#include <cuda_fp16.h>
#include <cstdint>
#include <math.h>

#define N_NODES 100000
#define N_EDGES 1600000
#define SCAN_BLOCKS 256
#define NTILES 782           // ceil(100000/128)
#define CHUNKS 4
#define TILES_PER_CHUNK 196
#define NODES_PER_CHUNK 25088   // 196*128
#define NBINS 512

// ---------------- scratch ----------------
__device__ int   g_deg[N_NODES];
__device__ float g_dinv[N_NODES];
__device__ int   g_rowptr[N_NODES + 1];
__device__ int   g_cursor[N_NODES];
__device__ int2  g_cw[N_EDGES];
__device__ int   g_blocksums[SCAN_BLOCKS];
__device__ int   g_hist[CHUNKS * NBINS];
__device__ int   g_perm[N_NODES];
__device__ __align__(16) __half g_h1h[(size_t)N_NODES * 128];
__device__ __align__(16) __half g_a1h[(size_t)N_NODES * 128];
__device__ __align__(16) __half g_h2h[(size_t)N_NODES * 64];
__device__ __align__(16) __nv_bfloat16 g_w1hi[128 * 128];
__device__ __align__(16) __nv_bfloat16 g_w1lo[128 * 128];
__device__ __align__(16) __nv_bfloat16 g_w2hi[64 * 128];
__device__ __align__(16) __nv_bfloat16 g_w2lo[64 * 128];

// ---------------- degree / scan / CSR ----------------
__global__ void k_count(const int4* __restrict__ dst4) {
    int i = blockIdx.x * 256 + threadIdx.x;
    if (i < N_EDGES / 4) {
        int4 d = __ldg(&dst4[i]);
        atomicAdd(&g_deg[d.x], 1);
        atomicAdd(&g_deg[d.y], 1);
        atomicAdd(&g_deg[d.z], 1);
        atomicAdd(&g_deg[d.w], 1);
    }
}

__global__ void k_scan_part() {
    __shared__ int wsum[16];
    int tid = threadIdx.x;
    int lane = tid & 31, wid = tid >> 5;
    int i = blockIdx.x * 512 + tid;
    int c = 0;
    if (i < N_NODES) {
        int d = g_deg[i];
        g_dinv[i] = rsqrtf((float)(d + 1));
        c = d;
    }
    int v = c;
    #pragma unroll
    for (int o = 1; o < 32; o <<= 1) {
        int t = __shfl_up_sync(0xffffffffu, v, o);
        if (lane >= o) v += t;
    }
    if (lane == 31) wsum[wid] = v;
    __syncthreads();
    if (wid == 0) {
        int s = (lane < 16) ? wsum[lane] : 0;
        #pragma unroll
        for (int o = 1; o < 16; o <<= 1) {
            int t = __shfl_up_sync(0xffffffffu, s, o);
            if (lane >= o) s += t;
        }
        if (lane < 16) wsum[lane] = s;
    }
    __syncthreads();
    int off = (wid > 0) ? wsum[wid - 1] : 0;
    if (i < N_NODES) g_rowptr[i] = off + v - c;
    if (tid == 511) g_blocksums[blockIdx.x] = wsum[15];
}

__global__ void k_scan_add2() {
    __shared__ int bs[SCAN_BLOCKS];
    __shared__ int pre[SCAN_BLOCKS];
    int tid = threadIdx.x;
    if (tid < SCAN_BLOCKS) bs[tid] = g_blocksums[tid];
    __syncthreads();
    if (tid < SCAN_BLOCKS) {
        int acc = 0;
        for (int j = 0; j < SCAN_BLOCKS; j++) {
            int v = bs[j];
            if (j < tid) acc += v;
        }
        pre[tid] = acc;
    }
    __syncthreads();
    int i = blockIdx.x * 512 + tid;
    if (i < N_NODES) {
        int r = g_rowptr[i] + pre[i >> 9];
        g_rowptr[i] = r;
        g_cursor[i] = r;
    }
    if (i == N_NODES) g_rowptr[N_NODES] = N_EDGES;
}

__global__ void k_fill(const int4* __restrict__ src4, const int4* __restrict__ dst4) {
    int i = blockIdx.x * 256 + threadIdx.x;
    if (i < N_EDGES / 4) {
        int4 s = __ldg(&src4[i]);
        int4 d = __ldg(&dst4[i]);
        int p0 = atomicAdd(&g_cursor[d.x], 1);
        g_cw[p0] = make_int2(s.x, __float_as_int(g_dinv[s.x]));
        int p1 = atomicAdd(&g_cursor[d.y], 1);
        g_cw[p1] = make_int2(s.y, __float_as_int(g_dinv[s.y]));
        int p2 = atomicAdd(&g_cursor[d.z], 1);
        g_cw[p2] = make_int2(s.z, __float_as_int(g_dinv[s.z]));
        int p3 = atomicAdd(&g_cursor[d.w], 1);
        g_cw[p3] = make_int2(s.w, __float_as_int(g_dinv[s.w]));
    }
}

// ---------------- degree-sorted permutation (per chunk, descending degree) ----------------
__global__ void k_hist() {
    int i = blockIdx.x * 256 + threadIdx.x;
    if (i < N_NODES) {
        int d = g_deg[i];
        if (d > NBINS - 1) d = NBINS - 1;
        int chunk = i / NODES_PER_CHUNK;
        atomicAdd(&g_hist[chunk * NBINS + d], 1);
    }
}

// 1 block, NBINS threads. Replaces bin counts with start cursors, positions
// ordered descending by degree within each chunk.
__global__ void k_hist_prefix() {
    __shared__ int bs[NBINS];
    int tid = threadIdx.x;
    for (int c = 0; c < CHUNKS; c++) {
        bs[tid] = g_hist[c * NBINS + (NBINS - 1 - tid)];  // reversed: heavy first
        __syncthreads();
        int acc = 0;
        for (int j = 0; j < tid; j++) acc += bs[j];
        g_hist[c * NBINS + (NBINS - 1 - tid)] = c * NODES_PER_CHUNK + acc;
        __syncthreads();
    }
}

__global__ void k_permute() {
    int i = blockIdx.x * 256 + threadIdx.x;
    if (i < N_NODES) {
        int d = g_deg[i];
        if (d > NBINS - 1) d = NBINS - 1;
        int chunk = i / NODES_PER_CHUNK;
        int pos = atomicAdd(&g_hist[chunk * NBINS + d], 1);
        g_perm[pos] = i;
    }
}

// ---------------- prep ----------------
__global__ void k_prep_w(const float* __restrict__ W1, const float* __restrict__ W2) {
    int i = blockIdx.x * 256 + threadIdx.x;
    if (i < 128 * 128) {
        int k = i >> 7, n = i & 127;
        float v = W1[i];
        __nv_bfloat16 h = __float2bfloat16(v);
        __nv_bfloat16 l = __float2bfloat16(v - __bfloat162float(h));
        g_w1hi[n * 128 + k] = h;
        g_w1lo[n * 128 + k] = l;
    } else if (i < 128 * 128 + 64 * 128) {
        int j = i - 128 * 128;
        int k = j >> 6, n = j & 63;
        float v = W2[j];
        __nv_bfloat16 h = __float2bfloat16(v);
        __nv_bfloat16 l = __float2bfloat16(v - __bfloat162float(h));
        g_w2hi[n * 128 + k] = h;
        g_w2lo[n * 128 + k] = l;
    }
}

// ---------------- helpers ----------------
__device__ __forceinline__ void mma_bf16(float& d0, float& d1, float& d2, float& d3,
                                         uint32_t a0, uint32_t a1, uint32_t a2, uint32_t a3,
                                         uint32_t b0, uint32_t b1) {
    asm volatile(
        "mma.sync.aligned.m16n8k16.row.col.f32.bf16.bf16.f32 "
        "{%0,%1,%2,%3}, {%4,%5,%6,%7}, {%8,%9}, {%0,%1,%2,%3};"
        : "+f"(d0), "+f"(d1), "+f"(d2), "+f"(d3)
        : "r"(a0), "r"(a1), "r"(a2), "r"(a3), "r"(b0), "r"(b1));
}
__device__ __forceinline__ uint32_t pack_hi2(float x, float y) {
    __nv_bfloat162 t = __halves2bfloat162(__float2bfloat16(x), __float2bfloat16(y));
    return *(uint32_t*)&t;
}
__device__ __forceinline__ uint32_t pack_lo2(float x, float y) {
    __nv_bfloat16 hx = __float2bfloat16(x), hy = __float2bfloat16(y);
    __nv_bfloat162 t = __halves2bfloat162(__float2bfloat16(x - __bfloat162float(hx)),
                                          __float2bfloat16(y - __bfloat162float(hy)));
    return *(uint32_t*)&t;
}
__device__ __forceinline__ void fma_h8(float* acc, float w, uint4 rv) {
    float2 f0 = __half22float2(*(__half2*)&rv.x);
    float2 f1 = __half22float2(*(__half2*)&rv.y);
    float2 f2 = __half22float2(*(__half2*)&rv.z);
    float2 f3 = __half22float2(*(__half2*)&rv.w);
    acc[0] = fmaf(w, f0.x, acc[0]);
    acc[1] = fmaf(w, f0.y, acc[1]);
    acc[2] = fmaf(w, f1.x, acc[2]);
    acc[3] = fmaf(w, f1.y, acc[3]);
    acc[4] = fmaf(w, f2.x, acc[4]);
    acc[5] = fmaf(w, f2.y, acc[5]);
    acc[6] = fmaf(w, f3.x, acc[6]);
    acc[7] = fmaf(w, f3.y, acc[7]);
}

// ---------------- GEMM (K split into two 64 halves; A smem halved) ----------------
template<int NOUT>
__global__ __launch_bounds__(256) void k_mma_gemm(const float* __restrict__ Ain, int tile0) {
    extern __shared__ uint32_t smu[];
    constexpr int STRA = 36;
    constexpr int STRB = 68;
    constexpr int WMG = (NOUT == 128) ? 2 : 4;
    constexpr int TM  = 128 / WMG;
    constexpr int MT  = TM / 16;
    constexpr int NT  = 4;

    uint32_t* As_hi = smu;
    uint32_t* As_lo = As_hi + 128 * STRA;
    uint32_t* Bs_hi = As_lo + 128 * STRA;
    uint32_t* Bs_lo = Bs_hi + NOUT * STRB;

    const int tid = threadIdx.x;
    const int wid = tid >> 5;
    const int lane = tid & 31;
    const int g = lane >> 2;
    const int tg = lane & 3;
    const int row0 = (tile0 + blockIdx.x) * 128;

    const uint32_t* WhG = (NOUT == 128) ? (const uint32_t*)g_w1hi : (const uint32_t*)g_w2hi;
    const uint32_t* WlG = (NOUT == 128) ? (const uint32_t*)g_w1lo : (const uint32_t*)g_w2lo;

    for (int i = tid; i < NOUT * 64; i += 256) {
        int n = i >> 6, kp = i & 63;
        Bs_hi[n * STRB + kp] = WhG[i];
        Bs_lo[n * STRB + kp] = WlG[i];
    }

    const int wm = (NOUT == 128) ? (wid & 1) : (wid & 3);
    const int wn = (NOUT == 128) ? (wid >> 1) : (wid >> 2);

    float d[MT][NT][4];
    #pragma unroll
    for (int mt = 0; mt < MT; mt++)
        #pragma unroll
        for (int nt = 0; nt < NT; nt++)
            #pragma unroll
            for (int j = 0; j < 4; j++) d[mt][nt][j] = 0.f;

    const float4* A4 = (const float4*)Ain;
    const uint2* A2h = (const uint2*)g_a1h;
    const uint32_t* Aterm[3] = {As_hi, As_hi, As_lo};
    const uint32_t* Bterm[3] = {Bs_hi, Bs_lo, Bs_hi};

    #pragma unroll
    for (int h = 0; h < 2; h++) {
        __syncthreads();
        #pragma unroll
        for (int t = 0; t < 8; t++) {
            int i = t * 256 + tid;
            int row = i >> 4, c4l = i & 15;
            int gr = row0 + row;
            float4 v = make_float4(0.f, 0.f, 0.f, 0.f);
            if (gr < N_NODES) {
                if (NOUT == 128) {
                    v = A4[(size_t)gr * 32 + h * 16 + c4l];
                } else {
                    uint2 hv = A2h[(size_t)gr * 32 + h * 16 + c4l];
                    float2 f0 = __half22float2(*(__half2*)&hv.x);
                    float2 f1 = __half22float2(*(__half2*)&hv.y);
                    v = make_float4(f0.x, f0.y, f1.x, f1.y);
                }
            }
            *(uint2*)&As_hi[row * STRA + c4l * 2] = make_uint2(pack_hi2(v.x, v.y), pack_hi2(v.z, v.w));
            *(uint2*)&As_lo[row * STRA + c4l * 2] = make_uint2(pack_lo2(v.x, v.y), pack_lo2(v.z, v.w));
        }
        __syncthreads();
        #pragma unroll
        for (int term = 0; term < 3; term++) {
            const uint32_t* Ab = Aterm[term] + (wm * TM + g) * STRA;
            const uint32_t* Bb = Bterm[term] + (wn * 32 + g) * STRB;
            #pragma unroll
            for (int ks = 0; ks < 4; ks++) {
                int koA = ks * 8 + tg;
                int koB = (h * 4 + ks) * 8 + tg;
                uint32_t a[MT][4], b[NT][2];
                #pragma unroll
                for (int mt = 0; mt < MT; mt++) {
                    const uint32_t* Ar = Ab + mt * 16 * STRA;
                    a[mt][0] = Ar[koA];
                    a[mt][1] = Ar[8 * STRA + koA];
                    a[mt][2] = Ar[koA + 4];
                    a[mt][3] = Ar[8 * STRA + koA + 4];
                }
                #pragma unroll
                for (int nt = 0; nt < NT; nt++) {
                    const uint32_t* Br = Bb + nt * 8 * STRB;
                    b[nt][0] = Br[koB];
                    b[nt][1] = Br[koB + 4];
                }
                #pragma unroll
                for (int mt = 0; mt < MT; mt++)
                    #pragma unroll
                    for (int nt = 0; nt < NT; nt++)
                        mma_bf16(d[mt][nt][0], d[mt][nt][1], d[mt][nt][2], d[mt][nt][3],
                                 a[mt][0], a[mt][1], a[mt][2], a[mt][3],
                                 b[nt][0], b[nt][1]);
            }
        }
    }

    #pragma unroll
    for (int mt = 0; mt < MT; mt++) {
        int r0 = row0 + wm * TM + mt * 16 + g;
        #pragma unroll
        for (int nt = 0; nt < NT; nt++) {
            int c = wn * 32 + nt * 8 + tg * 2;
            if (NOUT == 128) {
                if (r0 < N_NODES)
                    *(__half2*)&g_h1h[(size_t)r0 * 128 + c] =
                        __floats2half2_rn(d[mt][nt][0], d[mt][nt][1]);
                if (r0 + 8 < N_NODES)
                    *(__half2*)&g_h1h[(size_t)(r0 + 8) * 128 + c] =
                        __floats2half2_rn(d[mt][nt][2], d[mt][nt][3]);
            } else {
                if (r0 < N_NODES)
                    *(__half2*)&g_h2h[(size_t)r0 * 64 + c] =
                        __floats2half2_rn(d[mt][nt][0], d[mt][nt][1]);
                if (r0 + 8 < N_NODES)
                    *(__half2*)&g_h2h[(size_t)(r0 + 8) * 64 + c] =
                        __floats2half2_rn(d[mt][nt][2], d[mt][nt][3]);
            }
        }
    }
}

// ---------------- agg1: quarter-warp per (node, channel-half), degree-sorted ----------------
__global__ __launch_bounds__(256) void k_agg1(const float* __restrict__ b1,
                                              int node0, int node1) {
    int grp  = threadIdx.x >> 3;
    int gpos = node0 + blockIdx.x * 16 + (grp >> 1);
    if (gpos >= node1) return;
    int node = __ldg(&g_perm[gpos]);
    int half = grp & 1;
    int ql = threadIdx.x & 7;
    int col = half * 8 + ql;
    float di = g_dinv[node];
    const uint4* H = (const uint4*)g_h1h;
    float acc[8] = {0.f, 0.f, 0.f, 0.f, 0.f, 0.f, 0.f, 0.f};
    uint4 sv = __ldg(&H[(size_t)node * 16 + col]);
    fma_h8(acc, di, sv);
    int beg = g_rowptr[node];
    int end = g_rowptr[node + 1];
    #pragma unroll 4
    for (int e = beg; e < end; e++) {
        int2 cw = __ldg(&g_cw[e]);
        float w = __int_as_float(cw.y);
        uint4 hv = __ldg(&H[(size_t)cw.x * 16 + col]);
        fma_h8(acc, w, hv);
    }
    float4 bv0 = ((const float4*)b1)[col * 2];
    float4 bv1 = ((const float4*)b1)[col * 2 + 1];
    float o0 = fmaxf(fmaf(acc[0], di, bv0.x), 0.f);
    float o1 = fmaxf(fmaf(acc[1], di, bv0.y), 0.f);
    float o2 = fmaxf(fmaf(acc[2], di, bv0.z), 0.f);
    float o3 = fmaxf(fmaf(acc[3], di, bv0.w), 0.f);
    float o4 = fmaxf(fmaf(acc[4], di, bv1.x), 0.f);
    float o5 = fmaxf(fmaf(acc[5], di, bv1.y), 0.f);
    float o6 = fmaxf(fmaf(acc[6], di, bv1.z), 0.f);
    float o7 = fmaxf(fmaf(acc[7], di, bv1.w), 0.f);
    uint4 packed;
    *(__half2*)&packed.x = __floats2half2_rn(o0, o1);
    *(__half2*)&packed.y = __floats2half2_rn(o2, o3);
    *(__half2*)&packed.z = __floats2half2_rn(o4, o5);
    *(__half2*)&packed.w = __floats2half2_rn(o6, o7);
    ((uint4*)g_a1h)[(size_t)node * 16 + col] = packed;
}

// ---------------- agg2: quarter-warp per node, degree-sorted ----------------
__global__ __launch_bounds__(256) void k_agg2(const float* __restrict__ b2,
                                              float* __restrict__ out) {
    int gpos = blockIdx.x * 32 + (threadIdx.x >> 3);   // 3125*32 = 100000
    int node = __ldg(&g_perm[gpos]);
    int ql = threadIdx.x & 7;
    float di = g_dinv[node];
    const uint4* H = (const uint4*)g_h2h;
    float acc[8] = {0.f, 0.f, 0.f, 0.f, 0.f, 0.f, 0.f, 0.f};
    uint4 sv = __ldg(&H[(size_t)node * 8 + ql]);
    fma_h8(acc, di, sv);
    int beg = g_rowptr[node];
    int end = g_rowptr[node + 1];
    #pragma unroll 4
    for (int e = beg; e < end; e++) {
        int2 cw = __ldg(&g_cw[e]);
        float w = __int_as_float(cw.y);
        uint4 hv = __ldg(&H[(size_t)cw.x * 8 + ql]);
        fma_h8(acc, w, hv);
    }
    float4 bv0 = ((const float4*)b2)[ql * 2];
    float4 bv1 = ((const float4*)b2)[ql * 2 + 1];
    float v[8];
    v[0] = fmaf(acc[0], di, bv0.x);
    v[1] = fmaf(acc[1], di, bv0.y);
    v[2] = fmaf(acc[2], di, bv0.z);
    v[3] = fmaf(acc[3], di, bv0.w);
    v[4] = fmaf(acc[4], di, bv1.x);
    v[5] = fmaf(acc[5], di, bv1.y);
    v[6] = fmaf(acc[6], di, bv1.z);
    v[7] = fmaf(acc[7], di, bv1.w);

    float m = v[0];
    #pragma unroll
    for (int j = 1; j < 8; j++) m = fmaxf(m, v[j]);
    #pragma unroll
    for (int o = 4; o > 0; o >>= 1) m = fmaxf(m, __shfl_xor_sync(0xffffffffu, m, o));
    float s = 0.f;
    #pragma unroll
    for (int j = 0; j < 8; j++) s += expf(v[j] - m);
    #pragma unroll
    for (int o = 4; o > 0; o >>= 1) s += __shfl_xor_sync(0xffffffffu, s, o);
    float lse = m + logf(s);
    ((float4*)out)[(size_t)node * 16 + ql * 2] =
        make_float4(v[0] - lse, v[1] - lse, v[2] - lse, v[3] - lse);
    ((float4*)out)[(size_t)node * 16 + ql * 2 + 1] =
        make_float4(v[4] - lse, v[5] - lse, v[6] - lse, v[7] - lse);
}

// ---------------- launch ----------------
extern "C" void kernel_launch(void* const* d_in, const int* in_sizes, int n_in,
                              void* d_out, int out_size) {
    const float* x  = (const float*)d_in[0];
    const int*   ei = (const int*)d_in[1];
    const float* W1 = (const float*)d_in[2];
    const float* b1 = (const float*)d_in[3];
    const float* W2 = (const float*)d_in[4];
    const float* b2 = (const float*)d_in[5];
    float* out = (float*)d_out;

    const int4* src4 = (const int4*)ei;
    const int4* dst4 = (const int4*)(ei + N_EDGES);

    const int SMEM1 = (2 * 128 * 36 + 2 * 128 * 68) * 4;
    const int SMEM2 = (2 * 128 * 36 + 2 * 64 * 68) * 4;
    cudaFuncSetAttribute(k_mma_gemm<128>, cudaFuncAttributeMaxDynamicSharedMemorySize, SMEM1);
    cudaFuncSetAttribute(k_mma_gemm<64>,  cudaFuncAttributeMaxDynamicSharedMemorySize, SMEM2);

    void* degptr = nullptr;
    void* histptr = nullptr;
    cudaGetSymbolAddress(&degptr, g_deg);
    cudaGetSymbolAddress(&histptr, g_hist);

    cudaStream_t s1;
    cudaStreamCreateWithFlags(&s1, cudaStreamNonBlocking);
    cudaEvent_t evFork, evG1, evG2;
    cudaEvent_t evA[CHUNKS];
    cudaEventCreateWithFlags(&evFork, cudaEventDisableTiming);
    cudaEventCreateWithFlags(&evG1, cudaEventDisableTiming);
    cudaEventCreateWithFlags(&evG2, cudaEventDisableTiming);
    for (int c = 0; c < CHUNKS; c++) cudaEventCreateWithFlags(&evA[c], cudaEventDisableTiming);

    cudaEventRecord(evFork, 0);
    cudaStreamWaitEvent(s1, evFork, 0);

    // side stream: weight prep + GEMM1
    k_prep_w<<<(128 * 128 + 64 * 128 + 255) / 256, 256, 0, s1>>>(W1, W2);
    k_mma_gemm<128><<<NTILES, 256, SMEM1, s1>>>(x, 0);
    cudaEventRecord(evG1, s1);

    // main stream: CSR build + degree-sort permutation
    cudaMemsetAsync(degptr, 0, N_NODES * sizeof(int));
    cudaMemsetAsync(histptr, 0, CHUNKS * NBINS * sizeof(int));
    k_count<<<(N_EDGES / 4 + 255) / 256, 256>>>(dst4);
    k_hist<<<(N_NODES + 255) / 256, 256>>>();
    k_scan_part<<<SCAN_BLOCKS, 512>>>();
    k_hist_prefix<<<1, NBINS>>>();
    k_scan_add2<<<(N_NODES + 512) / 512, 512>>>();
    k_permute<<<(N_NODES + 255) / 256, 256>>>();
    k_fill<<<(N_EDGES / 4 + 255) / 256, 256>>>(src4, dst4);

    cudaStreamWaitEvent(0, evG1, 0);

    // pipelined agg1 (main) -> gemm2 chunk (side)
    for (int c = 0; c < CHUNKS; c++) {
        int t0 = c * TILES_PER_CHUNK;
        int t1 = (c == CHUNKS - 1) ? NTILES : (c + 1) * TILES_PER_CHUNK;
        int n0 = t0 * 128;
        int n1 = (t1 * 128 < N_NODES) ? t1 * 128 : N_NODES;
        int blocks = (n1 - n0 + 15) / 16;
        k_agg1<<<blocks, 256>>>(b1, n0, n1);
        cudaEventRecord(evA[c], 0);
        cudaStreamWaitEvent(s1, evA[c], 0);
        k_mma_gemm<64><<<t1 - t0, 256, SMEM2, s1>>>(nullptr, t0);
    }
    cudaEventRecord(evG2, s1);
    cudaStreamWaitEvent(0, evG2, 0);

    k_agg2<<<N_NODES / 32, 256>>>(b2, out);
}

// round 13
// speedup vs baseline: 1.1144x; 1.1144x over previous
#include <cuda_runtime.h>
#include <cuda_bf16.h>
#include <cuda_fp16.h>
#include <cstdint>
#include <math.h>

#define N_NODES 100000
#define N_EDGES 1600000
#define SCAN_BLOCKS 256
#define NTILES 782           // ceil(100000/128)
#define CHUNKS 4
#define TILES_PER_CHUNK 196

// ---------------- scratch ----------------
__device__ int   g_deg[N_NODES];
__device__ float g_dinv[N_NODES];
__device__ int   g_rowptr[N_NODES + 1];
__device__ int   g_cursor[N_NODES];
__device__ int2  g_cw[N_EDGES];
__device__ int   g_blocksums[SCAN_BLOCKS];
__device__ __align__(16) __half g_h1h[(size_t)N_NODES * 128];
__device__ __align__(16) __half g_a1h[(size_t)N_NODES * 128];
__device__ __align__(16) __half g_h2h[(size_t)N_NODES * 64];
__device__ __align__(16) __half g_w1hi[128 * 128];
__device__ __align__(16) __half g_w1lo[128 * 128];
__device__ __align__(16) __half g_w2hi[64 * 128];
__device__ __align__(16) __half g_w2lo[64 * 128];

// ---------------- degree / scan / CSR ----------------
__global__ void k_count(const int4* __restrict__ dst4) {
    int i = blockIdx.x * 256 + threadIdx.x;
    if (i < N_EDGES / 4) {
        int4 d = __ldg(&dst4[i]);
        atomicAdd(&g_deg[d.x], 1);
        atomicAdd(&g_deg[d.y], 1);
        atomicAdd(&g_deg[d.z], 1);
        atomicAdd(&g_deg[d.w], 1);
    }
}

__global__ void k_scan_part() {
    __shared__ int wsum[16];
    int tid = threadIdx.x;
    int lane = tid & 31, wid = tid >> 5;
    int i = blockIdx.x * 512 + tid;
    int c = 0;
    if (i < N_NODES) {
        int d = g_deg[i];
        g_dinv[i] = rsqrtf((float)(d + 1));
        c = d;
    }
    int v = c;
    #pragma unroll
    for (int o = 1; o < 32; o <<= 1) {
        int t = __shfl_up_sync(0xffffffffu, v, o);
        if (lane >= o) v += t;
    }
    if (lane == 31) wsum[wid] = v;
    __syncthreads();
    if (wid == 0) {
        int s = (lane < 16) ? wsum[lane] : 0;
        #pragma unroll
        for (int o = 1; o < 16; o <<= 1) {
            int t = __shfl_up_sync(0xffffffffu, s, o);
            if (lane >= o) s += t;
        }
        if (lane < 16) wsum[lane] = s;
    }
    __syncthreads();
    int off = (wid > 0) ? wsum[wid - 1] : 0;
    if (i < N_NODES) g_rowptr[i] = off + v - c;
    if (tid == 511) g_blocksums[blockIdx.x] = wsum[15];
}

__global__ void k_scan_add2() {
    __shared__ int bs[SCAN_BLOCKS];
    __shared__ int pre[SCAN_BLOCKS];
    int tid = threadIdx.x;
    if (tid < SCAN_BLOCKS) bs[tid] = g_blocksums[tid];
    __syncthreads();
    if (tid < SCAN_BLOCKS) {
        int acc = 0;
        for (int j = 0; j < SCAN_BLOCKS; j++) {
            int v = bs[j];
            if (j < tid) acc += v;
        }
        pre[tid] = acc;
    }
    __syncthreads();
    int i = blockIdx.x * 512 + tid;
    if (i < N_NODES) {
        int r = g_rowptr[i] + pre[i >> 9];
        g_rowptr[i] = r;
        g_cursor[i] = r;
    }
    if (i == N_NODES) g_rowptr[N_NODES] = N_EDGES;
}

__global__ void k_fill(const int4* __restrict__ src4, const int4* __restrict__ dst4) {
    int i = blockIdx.x * 256 + threadIdx.x;
    if (i < N_EDGES / 4) {
        int4 s = __ldg(&src4[i]);
        int4 d = __ldg(&dst4[i]);
        int p0 = atomicAdd(&g_cursor[d.x], 1);
        g_cw[p0] = make_int2(s.x, __float_as_int(g_dinv[s.x]));
        int p1 = atomicAdd(&g_cursor[d.y], 1);
        g_cw[p1] = make_int2(s.y, __float_as_int(g_dinv[s.y]));
        int p2 = atomicAdd(&g_cursor[d.z], 1);
        g_cw[p2] = make_int2(s.z, __float_as_int(g_dinv[s.z]));
        int p3 = atomicAdd(&g_cursor[d.w], 1);
        g_cw[p3] = make_int2(s.w, __float_as_int(g_dinv[s.w]));
    }
}

// ---------------- prep: split W into fp16 hi/lo, [n][k] orientation ----------------
__global__ void k_prep_w(const float* __restrict__ W1, const float* __restrict__ W2) {
    int i = blockIdx.x * 256 + threadIdx.x;
    if (i < 128 * 128) {
        int k = i >> 7, n = i & 127;
        float v = W1[i];
        __half h = __float2half_rn(v);
        __half l = __float2half_rn(v - __half2float(h));
        g_w1hi[n * 128 + k] = h;
        g_w1lo[n * 128 + k] = l;
    } else if (i < 128 * 128 + 64 * 128) {
        int j = i - 128 * 128;
        int k = j >> 6, n = j & 63;
        float v = W2[j];
        __half h = __float2half_rn(v);
        __half l = __float2half_rn(v - __half2float(h));
        g_w2hi[n * 128 + k] = h;
        g_w2lo[n * 128 + k] = l;
    }
}

// ---------------- helpers ----------------
__device__ __forceinline__ void mma_f16(float& d0, float& d1, float& d2, float& d3,
                                        uint32_t a0, uint32_t a1, uint32_t a2, uint32_t a3,
                                        uint32_t b0, uint32_t b1) {
    asm volatile(
        "mma.sync.aligned.m16n8k16.row.col.f32.f16.f16.f32 "
        "{%0,%1,%2,%3}, {%4,%5,%6,%7}, {%8,%9}, {%0,%1,%2,%3};"
        : "+f"(d0), "+f"(d1), "+f"(d2), "+f"(d3)
        : "r"(a0), "r"(a1), "r"(a2), "r"(a3), "r"(b0), "r"(b1));
}
__device__ __forceinline__ uint32_t packh_hi2(float x, float y) {
    __half2 t = __halves2half2(__float2half_rn(x), __float2half_rn(y));
    return *(uint32_t*)&t;
}
__device__ __forceinline__ uint32_t packh_lo2(float x, float y) {
    __half hx = __float2half_rn(x), hy = __float2half_rn(y);
    __half2 t = __halves2half2(__float2half_rn(x - __half2float(hx)),
                               __float2half_rn(y - __half2float(hy)));
    return *(uint32_t*)&t;
}
__device__ __forceinline__ void fma_h8(float* acc, float w, uint4 rv) {
    float2 f0 = __half22float2(*(__half2*)&rv.x);
    float2 f1 = __half22float2(*(__half2*)&rv.y);
    float2 f2 = __half22float2(*(__half2*)&rv.z);
    float2 f3 = __half22float2(*(__half2*)&rv.w);
    acc[0] = fmaf(w, f0.x, acc[0]);
    acc[1] = fmaf(w, f0.y, acc[1]);
    acc[2] = fmaf(w, f1.x, acc[2]);
    acc[3] = fmaf(w, f1.y, acc[3]);
    acc[4] = fmaf(w, f2.x, acc[4]);
    acc[5] = fmaf(w, f2.y, acc[5]);
    acc[6] = fmaf(w, f3.x, acc[6]);
    acc[7] = fmaf(w, f3.y, acc[7]);
}

// ---------------- GEMM1: h1h = x @ W1, 3-term fp16 hi/lo (K split in 2 halves) ----------------
__global__ __launch_bounds__(256) void k_gemm1(const float* __restrict__ Ain) {
    extern __shared__ uint32_t smu[];
    constexpr int STRA = 36;
    constexpr int STRB = 68;

    uint32_t* As_hi = smu;                     // 128*36
    uint32_t* As_lo = As_hi + 128 * STRA;
    uint32_t* Bs_hi = As_lo + 128 * STRA;      // 128*68
    uint32_t* Bs_lo = Bs_hi + 128 * STRB;

    const int tid = threadIdx.x;
    const int wid = tid >> 5;
    const int lane = tid & 31;
    const int g = lane >> 2;
    const int tg = lane & 3;
    const int row0 = blockIdx.x * 128;

    const uint32_t* WhG = (const uint32_t*)g_w1hi;
    const uint32_t* WlG = (const uint32_t*)g_w1lo;
    for (int i = tid; i < 128 * 64; i += 256) {
        int n = i >> 6, kp = i & 63;
        Bs_hi[n * STRB + kp] = WhG[i];
        Bs_lo[n * STRB + kp] = WlG[i];
    }

    const int wm = wid & 1;   // 2 M-groups of 64
    const int wn = wid >> 1;  // 4 N-groups of 32
    float d[4][4][4];
    #pragma unroll
    for (int mt = 0; mt < 4; mt++)
        #pragma unroll
        for (int nt = 0; nt < 4; nt++)
            #pragma unroll
            for (int j = 0; j < 4; j++) d[mt][nt][j] = 0.f;

    const float4* A4 = (const float4*)Ain;
    const uint32_t* Aterm[3] = {As_hi, As_hi, As_lo};
    const uint32_t* Bterm[3] = {Bs_hi, Bs_lo, Bs_hi};

    #pragma unroll
    for (int h = 0; h < 2; h++) {
        __syncthreads();
        #pragma unroll
        for (int t = 0; t < 8; t++) {
            int i = t * 256 + tid;
            int row = i >> 4, c4l = i & 15;
            int gr = row0 + row;
            float4 v = make_float4(0.f, 0.f, 0.f, 0.f);
            if (gr < N_NODES) v = A4[(size_t)gr * 32 + h * 16 + c4l];
            *(uint2*)&As_hi[row * STRA + c4l * 2] = make_uint2(packh_hi2(v.x, v.y), packh_hi2(v.z, v.w));
            *(uint2*)&As_lo[row * STRA + c4l * 2] = make_uint2(packh_lo2(v.x, v.y), packh_lo2(v.z, v.w));
        }
        __syncthreads();
        #pragma unroll
        for (int term = 0; term < 3; term++) {
            const uint32_t* Ab = Aterm[term] + (wm * 64 + g) * STRA;
            const uint32_t* Bb = Bterm[term] + (wn * 32 + g) * STRB;
            #pragma unroll
            for (int ks = 0; ks < 4; ks++) {
                int koA = ks * 8 + tg;
                int koB = (h * 4 + ks) * 8 + tg;
                uint32_t a[4][4], b[4][2];
                #pragma unroll
                for (int mt = 0; mt < 4; mt++) {
                    const uint32_t* Ar = Ab + mt * 16 * STRA;
                    a[mt][0] = Ar[koA];
                    a[mt][1] = Ar[8 * STRA + koA];
                    a[mt][2] = Ar[koA + 4];
                    a[mt][3] = Ar[8 * STRA + koA + 4];
                }
                #pragma unroll
                for (int nt = 0; nt < 4; nt++) {
                    const uint32_t* Br = Bb + nt * 8 * STRB;
                    b[nt][0] = Br[koB];
                    b[nt][1] = Br[koB + 4];
                }
                #pragma unroll
                for (int mt = 0; mt < 4; mt++)
                    #pragma unroll
                    for (int nt = 0; nt < 4; nt++)
                        mma_f16(d[mt][nt][0], d[mt][nt][1], d[mt][nt][2], d[mt][nt][3],
                                a[mt][0], a[mt][1], a[mt][2], a[mt][3],
                                b[nt][0], b[nt][1]);
            }
        }
    }

    #pragma unroll
    for (int mt = 0; mt < 4; mt++) {
        int r0 = row0 + wm * 64 + mt * 16 + g;
        #pragma unroll
        for (int nt = 0; nt < 4; nt++) {
            int c = wn * 32 + nt * 8 + tg * 2;
            if (r0 < N_NODES)
                *(__half2*)&g_h1h[(size_t)r0 * 128 + c] =
                    __floats2half2_rn(d[mt][nt][0], d[mt][nt][1]);
            if (r0 + 8 < N_NODES)
                *(__half2*)&g_h1h[(size_t)(r0 + 8) * 128 + c] =
                    __floats2half2_rn(d[mt][nt][2], d[mt][nt][3]);
        }
    }
}

// ---------------- GEMM2: h2h = a1h @ W2, 2-term (A fp16 exact; B fp16 hi/lo) ----------------
__global__ __launch_bounds__(256) void k_gemm2(int tile0) {
    extern __shared__ uint32_t smu[];
    constexpr int STRA = 36;
    constexpr int STRB = 68;

    uint32_t* As    = smu;                   // 128*36
    uint32_t* Bs_hi = As + 128 * STRA;       // 64*68
    uint32_t* Bs_lo = Bs_hi + 64 * STRB;

    const int tid = threadIdx.x;
    const int wid = tid >> 5;
    const int lane = tid & 31;
    const int g = lane >> 2;
    const int tg = lane & 3;
    const int row0 = (tile0 + blockIdx.x) * 128;

    const uint32_t* WhG = (const uint32_t*)g_w2hi;
    const uint32_t* WlG = (const uint32_t*)g_w2lo;
    for (int i = tid; i < 64 * 64; i += 256) {
        int n = i >> 6, kp = i & 63;
        Bs_hi[n * STRB + kp] = WhG[i];
        Bs_lo[n * STRB + kp] = WlG[i];
    }

    const int wm = wid & 3;   // 4 M-groups of 32
    const int wn = wid >> 2;  // 2 N-groups of 32
    float d[2][4][4];
    #pragma unroll
    for (int mt = 0; mt < 2; mt++)
        #pragma unroll
        for (int nt = 0; nt < 4; nt++)
            #pragma unroll
            for (int j = 0; j < 4; j++) d[mt][nt][j] = 0.f;

    const uint2* A2h = (const uint2*)g_a1h;  // 32 uint2 per row
    const uint32_t* Bterm[2] = {Bs_hi, Bs_lo};

    #pragma unroll
    for (int h = 0; h < 2; h++) {
        __syncthreads();
        // stage A half: plain copy, no conversion (a1h already fp16)
        #pragma unroll
        for (int t = 0; t < 8; t++) {
            int i = t * 256 + tid;
            int row = i >> 4, c4l = i & 15;
            int gr = row0 + row;
            uint2 v = make_uint2(0u, 0u);
            if (gr < N_NODES) v = A2h[(size_t)gr * 32 + h * 16 + c4l];
            *(uint2*)&As[row * STRA + c4l * 2] = v;
        }
        __syncthreads();
        #pragma unroll
        for (int term = 0; term < 2; term++) {
            const uint32_t* Ab = As + (wm * 32 + g) * STRA;
            const uint32_t* Bb = Bterm[term] + (wn * 32 + g) * STRB;
            #pragma unroll
            for (int ks = 0; ks < 4; ks++) {
                int koA = ks * 8 + tg;
                int koB = (h * 4 + ks) * 8 + tg;
                uint32_t a[2][4], b[4][2];
                #pragma unroll
                for (int mt = 0; mt < 2; mt++) {
                    const uint32_t* Ar = Ab + mt * 16 * STRA;
                    a[mt][0] = Ar[koA];
                    a[mt][1] = Ar[8 * STRA + koA];
                    a[mt][2] = Ar[koA + 4];
                    a[mt][3] = Ar[8 * STRA + koA + 4];
                }
                #pragma unroll
                for (int nt = 0; nt < 4; nt++) {
                    const uint32_t* Br = Bb + nt * 8 * STRB;
                    b[nt][0] = Br[koB];
                    b[nt][1] = Br[koB + 4];
                }
                #pragma unroll
                for (int mt = 0; mt < 2; mt++)
                    #pragma unroll
                    for (int nt = 0; nt < 4; nt++)
                        mma_f16(d[mt][nt][0], d[mt][nt][1], d[mt][nt][2], d[mt][nt][3],
                                a[mt][0], a[mt][1], a[mt][2], a[mt][3],
                                b[nt][0], b[nt][1]);
            }
        }
    }

    #pragma unroll
    for (int mt = 0; mt < 2; mt++) {
        int r0 = row0 + wm * 32 + mt * 16 + g;
        #pragma unroll
        for (int nt = 0; nt < 4; nt++) {
            int c = wn * 32 + nt * 8 + tg * 2;
            if (r0 < N_NODES)
                *(__half2*)&g_h2h[(size_t)r0 * 64 + c] =
                    __floats2half2_rn(d[mt][nt][0], d[mt][nt][1]);
            if (r0 + 8 < N_NODES)
                *(__half2*)&g_h2h[(size_t)(r0 + 8) * 64 + c] =
                    __floats2half2_rn(d[mt][nt][2], d[mt][nt][3]);
        }
    }
}

// ---------------- agg1: half-warp per node (16 lanes x uint4 = 256B row) ----------------
__global__ __launch_bounds__(256) void k_agg1(const float* __restrict__ b1,
                                              int node0, int node1) {
    int node = node0 + blockIdx.x * 16 + (threadIdx.x >> 4);
    if (node >= node1) return;
    int hl = threadIdx.x & 15;
    float di = g_dinv[node];
    const uint4* H = (const uint4*)g_h1h;
    float acc[8] = {0.f, 0.f, 0.f, 0.f, 0.f, 0.f, 0.f, 0.f};
    uint4 sv = __ldg(&H[(size_t)node * 16 + hl]);
    fma_h8(acc, di, sv);
    int beg = g_rowptr[node];
    int end = g_rowptr[node + 1];
    #pragma unroll 4
    for (int e = beg; e < end; e++) {
        int2 cw = __ldg(&g_cw[e]);
        float w = __int_as_float(cw.y);
        uint4 hv = __ldg(&H[(size_t)cw.x * 16 + hl]);
        fma_h8(acc, w, hv);
    }
    float4 bv0 = ((const float4*)b1)[hl * 2];
    float4 bv1 = ((const float4*)b1)[hl * 2 + 1];
    float o0 = fmaxf(fmaf(acc[0], di, bv0.x), 0.f);
    float o1 = fmaxf(fmaf(acc[1], di, bv0.y), 0.f);
    float o2 = fmaxf(fmaf(acc[2], di, bv0.z), 0.f);
    float o3 = fmaxf(fmaf(acc[3], di, bv0.w), 0.f);
    float o4 = fmaxf(fmaf(acc[4], di, bv1.x), 0.f);
    float o5 = fmaxf(fmaf(acc[5], di, bv1.y), 0.f);
    float o6 = fmaxf(fmaf(acc[6], di, bv1.z), 0.f);
    float o7 = fmaxf(fmaf(acc[7], di, bv1.w), 0.f);
    uint4 packed;
    *(__half2*)&packed.x = __floats2half2_rn(o0, o1);
    *(__half2*)&packed.y = __floats2half2_rn(o2, o3);
    *(__half2*)&packed.z = __floats2half2_rn(o4, o5);
    *(__half2*)&packed.w = __floats2half2_rn(o6, o7);
    ((uint4*)g_a1h)[(size_t)node * 16 + hl] = packed;
}

// ---------------- agg2: quarter-warp per node (8 lanes x uint4 = 128B row) ----------------
__global__ __launch_bounds__(256) void k_agg2(const float* __restrict__ b2,
                                              float* __restrict__ out) {
    int node = blockIdx.x * 32 + (threadIdx.x >> 3);   // 3125*32 = 100000
    int ql = threadIdx.x & 7;
    float di = g_dinv[node];
    const uint4* H = (const uint4*)g_h2h;
    float acc[8] = {0.f, 0.f, 0.f, 0.f, 0.f, 0.f, 0.f, 0.f};
    uint4 sv = __ldg(&H[(size_t)node * 8 + ql]);
    fma_h8(acc, di, sv);
    int beg = g_rowptr[node];
    int end = g_rowptr[node + 1];
    #pragma unroll 4
    for (int e = beg; e < end; e++) {
        int2 cw = __ldg(&g_cw[e]);
        float w = __int_as_float(cw.y);
        uint4 hv = __ldg(&H[(size_t)cw.x * 8 + ql]);
        fma_h8(acc, w, hv);
    }
    float4 bv0 = ((const float4*)b2)[ql * 2];
    float4 bv1 = ((const float4*)b2)[ql * 2 + 1];
    float v[8];
    v[0] = fmaf(acc[0], di, bv0.x);
    v[1] = fmaf(acc[1], di, bv0.y);
    v[2] = fmaf(acc[2], di, bv0.z);
    v[3] = fmaf(acc[3], di, bv0.w);
    v[4] = fmaf(acc[4], di, bv1.x);
    v[5] = fmaf(acc[5], di, bv1.y);
    v[6] = fmaf(acc[6], di, bv1.z);
    v[7] = fmaf(acc[7], di, bv1.w);

    float m = v[0];
    #pragma unroll
    for (int j = 1; j < 8; j++) m = fmaxf(m, v[j]);
    #pragma unroll
    for (int o = 4; o > 0; o >>= 1) m = fmaxf(m, __shfl_xor_sync(0xffffffffu, m, o));
    float s = 0.f;
    #pragma unroll
    for (int j = 0; j < 8; j++) s += expf(v[j] - m);
    #pragma unroll
    for (int o = 4; o > 0; o >>= 1) s += __shfl_xor_sync(0xffffffffu, s, o);
    float lse = m + logf(s);
    ((float4*)out)[(size_t)node * 16 + ql * 2] =
        make_float4(v[0] - lse, v[1] - lse, v[2] - lse, v[3] - lse);
    ((float4*)out)[(size_t)node * 16 + ql * 2 + 1] =
        make_float4(v[4] - lse, v[5] - lse, v[6] - lse, v[7] - lse);
}

// ---------------- launch ----------------
extern "C" void kernel_launch(void* const* d_in, const int* in_sizes, int n_in,
                              void* d_out, int out_size) {
    const float* x  = (const float*)d_in[0];
    const int*   ei = (const int*)d_in[1];
    const float* W1 = (const float*)d_in[2];
    const float* b1 = (const float*)d_in[3];
    const float* W2 = (const float*)d_in[4];
    const float* b2 = (const float*)d_in[5];
    float* out = (float*)d_out;

    const int4* src4 = (const int4*)ei;
    const int4* dst4 = (const int4*)(ei + N_EDGES);

    const int SMEM1 = (2 * 128 * 36 + 2 * 128 * 68) * 4;  // 106496
    const int SMEM2 = (128 * 36 + 2 * 64 * 68) * 4;       //  53248 -> 4 blocks/SM
    cudaFuncSetAttribute(k_gemm1, cudaFuncAttributeMaxDynamicSharedMemorySize, SMEM1);
    cudaFuncSetAttribute(k_gemm2, cudaFuncAttributeMaxDynamicSharedMemorySize, SMEM2);

    void* degptr = nullptr;
    cudaGetSymbolAddress(&degptr, g_deg);

    cudaStream_t s1;
    cudaStreamCreateWithFlags(&s1, cudaStreamNonBlocking);
    cudaEvent_t evFork, evG1, evG2;
    cudaEvent_t evA[CHUNKS];
    cudaEventCreateWithFlags(&evFork, cudaEventDisableTiming);
    cudaEventCreateWithFlags(&evG1, cudaEventDisableTiming);
    cudaEventCreateWithFlags(&evG2, cudaEventDisableTiming);
    for (int c = 0; c < CHUNKS; c++) cudaEventCreateWithFlags(&evA[c], cudaEventDisableTiming);

    cudaEventRecord(evFork, 0);
    cudaStreamWaitEvent(s1, evFork, 0);

    // side stream: weight prep + GEMM1
    k_prep_w<<<(128 * 128 + 64 * 128 + 255) / 256, 256, 0, s1>>>(W1, W2);
    k_gemm1<<<NTILES, 256, SMEM1, s1>>>(x);
    cudaEventRecord(evG1, s1);

    // main stream: CSR build
    cudaMemsetAsync(degptr, 0, N_NODES * sizeof(int));
    k_count<<<(N_EDGES / 4 + 255) / 256, 256>>>(dst4);
    k_scan_part<<<SCAN_BLOCKS, 512>>>();
    k_scan_add2<<<(N_NODES + 512) / 512, 512>>>();
    k_fill<<<(N_EDGES / 4 + 255) / 256, 256>>>(src4, dst4);

    cudaStreamWaitEvent(0, evG1, 0);

    // pipelined agg1 (main) -> gemm2 chunk (side)
    for (int c = 0; c < CHUNKS; c++) {
        int t0 = c * TILES_PER_CHUNK;
        int t1 = (c == CHUNKS - 1) ? NTILES : (c + 1) * TILES_PER_CHUNK;
        int n0 = t0 * 128;
        int n1 = (t1 * 128 < N_NODES) ? t1 * 128 : N_NODES;
        int blocks = (n1 - n0 + 15) / 16;
        k_agg1<<<blocks, 256>>>(b1, n0, n1);
        cudaEventRecord(evA[c], 0);
        cudaStreamWaitEvent(s1, evA[c], 0);
        k_gemm2<<<t1 - t0, 256, SMEM2, s1>>>(t0);
    }
    cudaEventRecord(evG2, s1);
    cudaStreamWaitEvent(0, evG2, 0);

    k_agg2<<<N_NODES / 32, 256>>>(b2, out);
}

// round 14
// speedup vs baseline: 1.1300x; 1.0140x over previous
#include <cuda_runtime.h>
#include <cuda_bf16.h>
#include <cuda_fp16.h>
#include <cstdint>
#include <math.h>

#define N_NODES 100000
#define N_EDGES 1600000
#define SCAN_BLOCKS 256
#define NTILES 782           // ceil(100000/128)
#define CHUNKS 4

// ---------------- scratch ----------------
__device__ int   g_deg[N_NODES];        // zeroed by k_fill tail each run (zero-init at load)
__device__ float g_dinv[N_NODES];
__device__ int   g_rowptr[N_NODES + 1];
__device__ int   g_cursor[N_NODES];
__device__ int2  g_cw[N_EDGES];
__device__ volatile unsigned long long g_bpack[SCAN_BLOCKS];  // (1<<32)|sum, zeroed by k_fill tail
__device__ __align__(16) __half g_h1h[(size_t)N_NODES * 128];
__device__ __align__(16) __half g_a1h[(size_t)N_NODES * 128];
__device__ __align__(16) __half g_h2h[(size_t)N_NODES * 64];
__device__ __align__(16) __half g_w1hi[128 * 128];
__device__ __align__(16) __half g_w1lo[128 * 128];
__device__ __align__(16) __half g_w2hi[64 * 128];
__device__ __align__(16) __half g_w2lo[64 * 128];

// ---------------- degree / fused scan / CSR ----------------
__global__ void k_count(const int4* __restrict__ dst4) {
    int i = blockIdx.x * 256 + threadIdx.x;
    if (i < N_EDGES / 4) {
        int4 d = __ldg(&dst4[i]);
        atomicAdd(&g_deg[d.x], 1);
        atomicAdd(&g_deg[d.y], 1);
        atomicAdd(&g_deg[d.z], 1);
        atomicAdd(&g_deg[d.w], 1);
    }
}

// fused scan: local block scan + decoupled lookback over lower block ids.
// Deadlock-free: a block spins only on lower bids, which are dispatched earlier.
__global__ void k_scan_fused() {
    __shared__ int wsum[16];
    __shared__ int s_prefix;
    int tid = threadIdx.x;
    int lane = tid & 31, wid = tid >> 5;
    int i = blockIdx.x * 512 + tid;
    int c = 0;
    if (i < N_NODES) {
        int d = g_deg[i];
        g_dinv[i] = rsqrtf((float)(d + 1));
        c = d;
    }
    int v = c;
    #pragma unroll
    for (int o = 1; o < 32; o <<= 1) {
        int t = __shfl_up_sync(0xffffffffu, v, o);
        if (lane >= o) v += t;
    }
    if (lane == 31) wsum[wid] = v;
    __syncthreads();
    if (wid == 0) {
        int s = (lane < 16) ? wsum[lane] : 0;
        #pragma unroll
        for (int o = 1; o < 16; o <<= 1) {
            int t = __shfl_up_sync(0xffffffffu, s, o);
            if (lane >= o) s += t;
        }
        if (lane < 16) wsum[lane] = s;
    }
    __syncthreads();
    int total = wsum[15];

    // publish local block sum (packed with nonzero flag bit)
    if (tid == 0)
        g_bpack[blockIdx.x] = (1ull << 32) | (unsigned long long)(unsigned)total;

    // warp 0: sum all predecessor block sums (warp-parallel spin)
    if (wid == 0) {
        int acc = 0;
        int nb = blockIdx.x;
        for (int base = 0; base < nb; base += 32) {
            int j = base + lane;
            int s = 0;
            if (j < nb) {
                unsigned long long p;
                do { p = g_bpack[j]; } while (p == 0ull);
                s = (int)(unsigned)p;
            }
            #pragma unroll
            for (int o = 16; o > 0; o >>= 1) s += __shfl_xor_sync(0xffffffffu, s, o);
            acc += s;
        }
        if (lane == 0) s_prefix = acc;
    }
    __syncthreads();

    int off = (wid > 0) ? wsum[wid - 1] : 0;
    if (i < N_NODES) {
        int r = s_prefix + off + v - c;
        g_rowptr[i] = r;
        g_cursor[i] = r;
    }
    if (i == N_NODES) g_rowptr[N_NODES] = N_EDGES;
}

__global__ void k_fill(const int4* __restrict__ src4, const int4* __restrict__ dst4) {
    int i = blockIdx.x * 256 + threadIdx.x;
    if (i < N_EDGES / 4) {
        int4 s = __ldg(&src4[i]);
        int4 d = __ldg(&dst4[i]);
        int p0 = atomicAdd(&g_cursor[d.x], 1);
        g_cw[p0] = make_int2(s.x, __float_as_int(g_dinv[s.x]));
        int p1 = atomicAdd(&g_cursor[d.y], 1);
        g_cw[p1] = make_int2(s.y, __float_as_int(g_dinv[s.y]));
        int p2 = atomicAdd(&g_cursor[d.z], 1);
        g_cw[p2] = make_int2(s.z, __float_as_int(g_dinv[s.z]));
        int p3 = atomicAdd(&g_cursor[d.w], 1);
        g_cw[p3] = make_int2(s.w, __float_as_int(g_dinv[s.w]));
    }
    // reset state for the next graph replay (deg counted fresh; scan flags cleared)
    if (i < N_NODES) g_deg[i] = 0;
    if (i < SCAN_BLOCKS) g_bpack[i] = 0ull;
}

// ---------------- prep: split W into fp16 hi/lo, [n][k] orientation ----------------
__global__ void k_prep_w(const float* __restrict__ W1, const float* __restrict__ W2) {
    int i = blockIdx.x * 256 + threadIdx.x;
    if (i < 128 * 128) {
        int k = i >> 7, n = i & 127;
        float v = W1[i];
        __half h = __float2half_rn(v);
        __half l = __float2half_rn(v - __half2float(h));
        g_w1hi[n * 128 + k] = h;
        g_w1lo[n * 128 + k] = l;
    } else if (i < 128 * 128 + 64 * 128) {
        int j = i - 128 * 128;
        int k = j >> 6, n = j & 63;
        float v = W2[j];
        __half h = __float2half_rn(v);
        __half l = __float2half_rn(v - __half2float(h));
        g_w2hi[n * 128 + k] = h;
        g_w2lo[n * 128 + k] = l;
    }
}

// ---------------- helpers ----------------
__device__ __forceinline__ void mma_f16(float& d0, float& d1, float& d2, float& d3,
                                        uint32_t a0, uint32_t a1, uint32_t a2, uint32_t a3,
                                        uint32_t b0, uint32_t b1) {
    asm volatile(
        "mma.sync.aligned.m16n8k16.row.col.f32.f16.f16.f32 "
        "{%0,%1,%2,%3}, {%4,%5,%6,%7}, {%8,%9}, {%0,%1,%2,%3};"
        : "+f"(d0), "+f"(d1), "+f"(d2), "+f"(d3)
        : "r"(a0), "r"(a1), "r"(a2), "r"(a3), "r"(b0), "r"(b1));
}
__device__ __forceinline__ uint32_t packh_hi2(float x, float y) {
    __half2 t = __halves2half2(__float2half_rn(x), __float2half_rn(y));
    return *(uint32_t*)&t;
}
__device__ __forceinline__ uint32_t packh_lo2(float x, float y) {
    __half hx = __float2half_rn(x), hy = __float2half_rn(y);
    __half2 t = __halves2half2(__float2half_rn(x - __half2float(hx)),
                               __float2half_rn(y - __half2float(hy)));
    return *(uint32_t*)&t;
}
__device__ __forceinline__ void fma_h8(float* acc, float w, uint4 rv) {
    float2 f0 = __half22float2(*(__half2*)&rv.x);
    float2 f1 = __half22float2(*(__half2*)&rv.y);
    float2 f2 = __half22float2(*(__half2*)&rv.z);
    float2 f3 = __half22float2(*(__half2*)&rv.w);
    acc[0] = fmaf(w, f0.x, acc[0]);
    acc[1] = fmaf(w, f0.y, acc[1]);
    acc[2] = fmaf(w, f1.x, acc[2]);
    acc[3] = fmaf(w, f1.y, acc[3]);
    acc[4] = fmaf(w, f2.x, acc[4]);
    acc[5] = fmaf(w, f2.y, acc[5]);
    acc[6] = fmaf(w, f3.x, acc[6]);
    acc[7] = fmaf(w, f3.y, acc[7]);
}

// ---------------- GEMM1: h1h = x @ W1, 3-term fp16 hi/lo (K split in 2 halves) ----------------
__global__ __launch_bounds__(256) void k_gemm1(const float* __restrict__ Ain) {
    extern __shared__ uint32_t smu[];
    constexpr int STRA = 36;
    constexpr int STRB = 68;

    uint32_t* As_hi = smu;
    uint32_t* As_lo = As_hi + 128 * STRA;
    uint32_t* Bs_hi = As_lo + 128 * STRA;
    uint32_t* Bs_lo = Bs_hi + 128 * STRB;

    const int tid = threadIdx.x;
    const int wid = tid >> 5;
    const int lane = tid & 31;
    const int g = lane >> 2;
    const int tg = lane & 3;
    const int row0 = blockIdx.x * 128;

    const uint32_t* WhG = (const uint32_t*)g_w1hi;
    const uint32_t* WlG = (const uint32_t*)g_w1lo;
    for (int i = tid; i < 128 * 64; i += 256) {
        int n = i >> 6, kp = i & 63;
        Bs_hi[n * STRB + kp] = WhG[i];
        Bs_lo[n * STRB + kp] = WlG[i];
    }

    const int wm = wid & 1;
    const int wn = wid >> 1;
    float d[4][4][4];
    #pragma unroll
    for (int mt = 0; mt < 4; mt++)
        #pragma unroll
        for (int nt = 0; nt < 4; nt++)
            #pragma unroll
            for (int j = 0; j < 4; j++) d[mt][nt][j] = 0.f;

    const float4* A4 = (const float4*)Ain;
    const uint32_t* Aterm[3] = {As_hi, As_hi, As_lo};
    const uint32_t* Bterm[3] = {Bs_hi, Bs_lo, Bs_hi};

    #pragma unroll
    for (int h = 0; h < 2; h++) {
        __syncthreads();
        #pragma unroll
        for (int t = 0; t < 8; t++) {
            int i = t * 256 + tid;
            int row = i >> 4, c4l = i & 15;
            int gr = row0 + row;
            float4 v = make_float4(0.f, 0.f, 0.f, 0.f);
            if (gr < N_NODES) v = A4[(size_t)gr * 32 + h * 16 + c4l];
            *(uint2*)&As_hi[row * STRA + c4l * 2] = make_uint2(packh_hi2(v.x, v.y), packh_hi2(v.z, v.w));
            *(uint2*)&As_lo[row * STRA + c4l * 2] = make_uint2(packh_lo2(v.x, v.y), packh_lo2(v.z, v.w));
        }
        __syncthreads();
        #pragma unroll
        for (int term = 0; term < 3; term++) {
            const uint32_t* Ab = Aterm[term] + (wm * 64 + g) * STRA;
            const uint32_t* Bb = Bterm[term] + (wn * 32 + g) * STRB;
            #pragma unroll
            for (int ks = 0; ks < 4; ks++) {
                int koA = ks * 8 + tg;
                int koB = (h * 4 + ks) * 8 + tg;
                uint32_t a[4][4], b[4][2];
                #pragma unroll
                for (int mt = 0; mt < 4; mt++) {
                    const uint32_t* Ar = Ab + mt * 16 * STRA;
                    a[mt][0] = Ar[koA];
                    a[mt][1] = Ar[8 * STRA + koA];
                    a[mt][2] = Ar[koA + 4];
                    a[mt][3] = Ar[8 * STRA + koA + 4];
                }
                #pragma unroll
                for (int nt = 0; nt < 4; nt++) {
                    const uint32_t* Br = Bb + nt * 8 * STRB;
                    b[nt][0] = Br[koB];
                    b[nt][1] = Br[koB + 4];
                }
                #pragma unroll
                for (int mt = 0; mt < 4; mt++)
                    #pragma unroll
                    for (int nt = 0; nt < 4; nt++)
                        mma_f16(d[mt][nt][0], d[mt][nt][1], d[mt][nt][2], d[mt][nt][3],
                                a[mt][0], a[mt][1], a[mt][2], a[mt][3],
                                b[nt][0], b[nt][1]);
            }
        }
    }

    #pragma unroll
    for (int mt = 0; mt < 4; mt++) {
        int r0 = row0 + wm * 64 + mt * 16 + g;
        #pragma unroll
        for (int nt = 0; nt < 4; nt++) {
            int c = wn * 32 + nt * 8 + tg * 2;
            if (r0 < N_NODES)
                *(__half2*)&g_h1h[(size_t)r0 * 128 + c] =
                    __floats2half2_rn(d[mt][nt][0], d[mt][nt][1]);
            if (r0 + 8 < N_NODES)
                *(__half2*)&g_h1h[(size_t)(r0 + 8) * 128 + c] =
                    __floats2half2_rn(d[mt][nt][2], d[mt][nt][3]);
        }
    }
}

// ---------------- GEMM2: h2h = a1h @ W2, 2-term (A fp16 exact; B fp16 hi/lo) ----------------
__global__ __launch_bounds__(256) void k_gemm2(int tile0) {
    extern __shared__ uint32_t smu[];
    constexpr int STRA = 36;
    constexpr int STRB = 68;

    uint32_t* As    = smu;
    uint32_t* Bs_hi = As + 128 * STRA;
    uint32_t* Bs_lo = Bs_hi + 64 * STRB;

    const int tid = threadIdx.x;
    const int wid = tid >> 5;
    const int lane = tid & 31;
    const int g = lane >> 2;
    const int tg = lane & 3;
    const int row0 = (tile0 + blockIdx.x) * 128;

    const uint32_t* WhG = (const uint32_t*)g_w2hi;
    const uint32_t* WlG = (const uint32_t*)g_w2lo;
    for (int i = tid; i < 64 * 64; i += 256) {
        int n = i >> 6, kp = i & 63;
        Bs_hi[n * STRB + kp] = WhG[i];
        Bs_lo[n * STRB + kp] = WlG[i];
    }

    const int wm = wid & 3;
    const int wn = wid >> 2;
    float d[2][4][4];
    #pragma unroll
    for (int mt = 0; mt < 2; mt++)
        #pragma unroll
        for (int nt = 0; nt < 4; nt++)
            #pragma unroll
            for (int j = 0; j < 4; j++) d[mt][nt][j] = 0.f;

    const uint2* A2h = (const uint2*)g_a1h;
    const uint32_t* Bterm[2] = {Bs_hi, Bs_lo};

    #pragma unroll
    for (int h = 0; h < 2; h++) {
        __syncthreads();
        #pragma unroll
        for (int t = 0; t < 8; t++) {
            int i = t * 256 + tid;
            int row = i >> 4, c4l = i & 15;
            int gr = row0 + row;
            uint2 v = make_uint2(0u, 0u);
            if (gr < N_NODES) v = A2h[(size_t)gr * 32 + h * 16 + c4l];
            *(uint2*)&As[row * STRA + c4l * 2] = v;
        }
        __syncthreads();
        #pragma unroll
        for (int term = 0; term < 2; term++) {
            const uint32_t* Ab = As + (wm * 32 + g) * STRA;
            const uint32_t* Bb = Bterm[term] + (wn * 32 + g) * STRB;
            #pragma unroll
            for (int ks = 0; ks < 4; ks++) {
                int koA = ks * 8 + tg;
                int koB = (h * 4 + ks) * 8 + tg;
                uint32_t a[2][4], b[4][2];
                #pragma unroll
                for (int mt = 0; mt < 2; mt++) {
                    const uint32_t* Ar = Ab + mt * 16 * STRA;
                    a[mt][0] = Ar[koA];
                    a[mt][1] = Ar[8 * STRA + koA];
                    a[mt][2] = Ar[koA + 4];
                    a[mt][3] = Ar[8 * STRA + koA + 4];
                }
                #pragma unroll
                for (int nt = 0; nt < 4; nt++) {
                    const uint32_t* Br = Bb + nt * 8 * STRB;
                    b[nt][0] = Br[koB];
                    b[nt][1] = Br[koB + 4];
                }
                #pragma unroll
                for (int mt = 0; mt < 2; mt++)
                    #pragma unroll
                    for (int nt = 0; nt < 4; nt++)
                        mma_f16(d[mt][nt][0], d[mt][nt][1], d[mt][nt][2], d[mt][nt][3],
                                a[mt][0], a[mt][1], a[mt][2], a[mt][3],
                                b[nt][0], b[nt][1]);
            }
        }
    }

    #pragma unroll
    for (int mt = 0; mt < 2; mt++) {
        int r0 = row0 + wm * 32 + mt * 16 + g;
        #pragma unroll
        for (int nt = 0; nt < 4; nt++) {
            int c = wn * 32 + nt * 8 + tg * 2;
            if (r0 < N_NODES)
                *(__half2*)&g_h2h[(size_t)r0 * 64 + c] =
                    __floats2half2_rn(d[mt][nt][0], d[mt][nt][1]);
            if (r0 + 8 < N_NODES)
                *(__half2*)&g_h2h[(size_t)(r0 + 8) * 64 + c] =
                    __floats2half2_rn(d[mt][nt][2], d[mt][nt][3]);
        }
    }
}

// ---------------- agg1: half-warp per node (16 lanes x uint4 = 256B row) ----------------
__global__ __launch_bounds__(256) void k_agg1(const float* __restrict__ b1,
                                              int node0, int node1) {
    int node = node0 + blockIdx.x * 16 + (threadIdx.x >> 4);
    if (node >= node1) return;
    int hl = threadIdx.x & 15;
    float di = g_dinv[node];
    const uint4* H = (const uint4*)g_h1h;
    float acc[8] = {0.f, 0.f, 0.f, 0.f, 0.f, 0.f, 0.f, 0.f};
    uint4 sv = __ldg(&H[(size_t)node * 16 + hl]);
    fma_h8(acc, di, sv);
    int beg = g_rowptr[node];
    int end = g_rowptr[node + 1];
    #pragma unroll 4
    for (int e = beg; e < end; e++) {
        int2 cw = __ldg(&g_cw[e]);
        float w = __int_as_float(cw.y);
        uint4 hv = __ldg(&H[(size_t)cw.x * 16 + hl]);
        fma_h8(acc, w, hv);
    }
    float4 bv0 = ((const float4*)b1)[hl * 2];
    float4 bv1 = ((const float4*)b1)[hl * 2 + 1];
    float o0 = fmaxf(fmaf(acc[0], di, bv0.x), 0.f);
    float o1 = fmaxf(fmaf(acc[1], di, bv0.y), 0.f);
    float o2 = fmaxf(fmaf(acc[2], di, bv0.z), 0.f);
    float o3 = fmaxf(fmaf(acc[3], di, bv0.w), 0.f);
    float o4 = fmaxf(fmaf(acc[4], di, bv1.x), 0.f);
    float o5 = fmaxf(fmaf(acc[5], di, bv1.y), 0.f);
    float o6 = fmaxf(fmaf(acc[6], di, bv1.z), 0.f);
    float o7 = fmaxf(fmaf(acc[7], di, bv1.w), 0.f);
    uint4 packed;
    *(__half2*)&packed.x = __floats2half2_rn(o0, o1);
    *(__half2*)&packed.y = __floats2half2_rn(o2, o3);
    *(__half2*)&packed.z = __floats2half2_rn(o4, o5);
    *(__half2*)&packed.w = __floats2half2_rn(o6, o7);
    ((uint4*)g_a1h)[(size_t)node * 16 + hl] = packed;
}

// ---------------- agg2: quarter-warp per node (8 lanes x uint4 = 128B row) ----------------
__global__ __launch_bounds__(256) void k_agg2(const float* __restrict__ b2,
                                              float* __restrict__ out) {
    int node = blockIdx.x * 32 + (threadIdx.x >> 3);   // 3125*32 = 100000
    int ql = threadIdx.x & 7;
    float di = g_dinv[node];
    const uint4* H = (const uint4*)g_h2h;
    float acc[8] = {0.f, 0.f, 0.f, 0.f, 0.f, 0.f, 0.f, 0.f};
    uint4 sv = __ldg(&H[(size_t)node * 8 + ql]);
    fma_h8(acc, di, sv);
    int beg = g_rowptr[node];
    int end = g_rowptr[node + 1];
    #pragma unroll 4
    for (int e = beg; e < end; e++) {
        int2 cw = __ldg(&g_cw[e]);
        float w = __int_as_float(cw.y);
        uint4 hv = __ldg(&H[(size_t)cw.x * 8 + ql]);
        fma_h8(acc, w, hv);
    }
    float4 bv0 = ((const float4*)b2)[ql * 2];
    float4 bv1 = ((const float4*)b2)[ql * 2 + 1];
    float v[8];
    v[0] = fmaf(acc[0], di, bv0.x);
    v[1] = fmaf(acc[1], di, bv0.y);
    v[2] = fmaf(acc[2], di, bv0.z);
    v[3] = fmaf(acc[3], di, bv0.w);
    v[4] = fmaf(acc[4], di, bv1.x);
    v[5] = fmaf(acc[5], di, bv1.y);
    v[6] = fmaf(acc[6], di, bv1.z);
    v[7] = fmaf(acc[7], di, bv1.w);

    float m = v[0];
    #pragma unroll
    for (int j = 1; j < 8; j++) m = fmaxf(m, v[j]);
    #pragma unroll
    for (int o = 4; o > 0; o >>= 1) m = fmaxf(m, __shfl_xor_sync(0xffffffffu, m, o));
    float s = 0.f;
    #pragma unroll
    for (int j = 0; j < 8; j++) s += expf(v[j] - m);
    #pragma unroll
    for (int o = 4; o > 0; o >>= 1) s += __shfl_xor_sync(0xffffffffu, s, o);
    float lse = m + logf(s);
    ((float4*)out)[(size_t)node * 16 + ql * 2] =
        make_float4(v[0] - lse, v[1] - lse, v[2] - lse, v[3] - lse);
    ((float4*)out)[(size_t)node * 16 + ql * 2 + 1] =
        make_float4(v[4] - lse, v[5] - lse, v[6] - lse, v[7] - lse);
}

// ---------------- launch ----------------
extern "C" void kernel_launch(void* const* d_in, const int* in_sizes, int n_in,
                              void* d_out, int out_size) {
    const float* x  = (const float*)d_in[0];
    const int*   ei = (const int*)d_in[1];
    const float* W1 = (const float*)d_in[2];
    const float* b1 = (const float*)d_in[3];
    const float* W2 = (const float*)d_in[4];
    const float* b2 = (const float*)d_in[5];
    float* out = (float*)d_out;

    const int4* src4 = (const int4*)ei;
    const int4* dst4 = (const int4*)(ei + N_EDGES);

    const int SMEM1 = (2 * 128 * 36 + 2 * 128 * 68) * 4;  // 106496
    const int SMEM2 = (128 * 36 + 2 * 64 * 68) * 4;       //  53248
    cudaFuncSetAttribute(k_gemm1, cudaFuncAttributeMaxDynamicSharedMemorySize, SMEM1);
    cudaFuncSetAttribute(k_gemm2, cudaFuncAttributeMaxDynamicSharedMemorySize, SMEM2);

    cudaStream_t s1;
    cudaStreamCreateWithFlags(&s1, cudaStreamNonBlocking);
    cudaEvent_t evFork, evG1, evG2;
    cudaEvent_t evA[CHUNKS];
    cudaEventCreateWithFlags(&evFork, cudaEventDisableTiming);
    cudaEventCreateWithFlags(&evG1, cudaEventDisableTiming);
    cudaEventCreateWithFlags(&evG2, cudaEventDisableTiming);
    for (int c = 0; c < CHUNKS; c++) cudaEventCreateWithFlags(&evA[c], cudaEventDisableTiming);

    cudaEventRecord(evFork, 0);
    cudaStreamWaitEvent(s1, evFork, 0);

    // side stream: weight prep + GEMM1
    k_prep_w<<<(128 * 128 + 64 * 128 + 255) / 256, 256, 0, s1>>>(W1, W2);
    k_gemm1<<<NTILES, 256, SMEM1, s1>>>(x);
    cudaEventRecord(evG1, s1);

    // main stream: CSR build (3 launches: count, fused scan, fill)
    k_count<<<(N_EDGES / 4 + 255) / 256, 256>>>(dst4);
    k_scan_fused<<<SCAN_BLOCKS, 512>>>();
    k_fill<<<(N_EDGES / 4 + 255) / 256, 256>>>(src4, dst4);

    cudaStreamWaitEvent(0, evG1, 0);

    // pipelined agg1 (main) -> gemm2 chunk (side); descending chunk sizes shrink the tail
    const int chunkTiles[CHUNKS] = {216, 216, 216, 134};
    int t0 = 0;
    for (int c = 0; c < CHUNKS; c++) {
        int t1 = t0 + chunkTiles[c];
        int n0 = t0 * 128;
        int n1 = (t1 * 128 < N_NODES) ? t1 * 128 : N_NODES;
        int blocks = (n1 - n0 + 15) / 16;
        k_agg1<<<blocks, 256>>>(b1, n0, n1);
        cudaEventRecord(evA[c], 0);
        cudaStreamWaitEvent(s1, evA[c], 0);
        k_gemm2<<<t1 - t0, 256, SMEM2, s1>>>(t0);
        t0 = t1;
    }
    cudaEventRecord(evG2, s1);
    cudaStreamWaitEvent(0, evG2, 0);

    k_agg2<<<N_NODES / 32, 256>>>(b2, out);
}

// round 15
// speedup vs baseline: 1.1570x; 1.0239x over previous
#include <cuda_runtime.h>
#include <cuda_bf16.h>
#include <cuda_fp16.h>
#include <cstdint>
#include <math.h>

#define N_NODES 100000
#define N_EDGES 1600000
#define NTILES 782           // ceil(100000/128)
#define CHUNKS 4

// ---------------- scratch ----------------
__device__ int   g_deg[N_NODES];        // zeroed by k_fill tail each run (zero-init at load)
__device__ int   g_alloc;               // arrival-order segment allocator (zeroed by k_fill tail)
__device__ float g_dinv[N_NODES];
__device__ int2  g_seg[N_NODES];        // (beg, end) of each node's edge segment
__device__ int   g_cursor[N_NODES];
__device__ int2  g_cw[N_EDGES];
__device__ __align__(16) __half g_h1h[(size_t)N_NODES * 128];
__device__ __align__(16) __half g_a1h[(size_t)N_NODES * 128];
__device__ __align__(16) __half g_h2h[(size_t)N_NODES * 64];
__device__ __align__(16) __half g_w1hi[128 * 128];
__device__ __align__(16) __half g_w1lo[128 * 128];
__device__ __align__(16) __half g_w2hi[64 * 128];
__device__ __align__(16) __half g_w2lo[64 * 128];

// ---------------- degree / scan / CSR ----------------
__global__ void k_count(const int4* __restrict__ dst4) {
    int i = blockIdx.x * 256 + threadIdx.x;
    if (i < N_EDGES / 4) {
        int4 d = __ldg(&dst4[i]);
        atomicAdd(&g_deg[d.x], 1);
        atomicAdd(&g_deg[d.y], 1);
        atomicAdd(&g_deg[d.z], 1);
        atomicAdd(&g_deg[d.w], 1);
    }
}

// single-pass scan: block-local prefix + ONE atomicAdd for the block offset
// (arrival-order segment placement; contiguity across blocks not required
// because aggs read explicit per-node (beg,end) segments).
__global__ void k_scan_alloc() {
    __shared__ int wsum[16];
    __shared__ int s_base;
    int tid = threadIdx.x;
    int lane = tid & 31, wid = tid >> 5;
    int i = blockIdx.x * 512 + tid;
    int c = 0;
    if (i < N_NODES) {
        int d = g_deg[i];
        g_dinv[i] = rsqrtf((float)(d + 1));
        c = d;
    }
    int v = c;
    #pragma unroll
    for (int o = 1; o < 32; o <<= 1) {
        int t = __shfl_up_sync(0xffffffffu, v, o);
        if (lane >= o) v += t;
    }
    if (lane == 31) wsum[wid] = v;
    __syncthreads();
    if (wid == 0) {
        int s = (lane < 16) ? wsum[lane] : 0;
        #pragma unroll
        for (int o = 1; o < 16; o <<= 1) {
            int t = __shfl_up_sync(0xffffffffu, s, o);
            if (lane >= o) s += t;
        }
        if (lane < 16) wsum[lane] = s;
    }
    __syncthreads();
    if (tid == 0) s_base = atomicAdd(&g_alloc, wsum[15]);
    __syncthreads();
    int off = (wid > 0) ? wsum[wid - 1] : 0;
    if (i < N_NODES) {
        int beg = s_base + off + v - c;
        g_seg[i] = make_int2(beg, beg + c);
        g_cursor[i] = beg;
    }
}

__global__ void k_fill(const int4* __restrict__ src4, const int4* __restrict__ dst4) {
    int i = blockIdx.x * 256 + threadIdx.x;
    if (i < N_EDGES / 4) {
        int4 s = __ldg(&src4[i]);
        int4 d = __ldg(&dst4[i]);
        int p0 = atomicAdd(&g_cursor[d.x], 1);
        g_cw[p0] = make_int2(s.x, __float_as_int(g_dinv[s.x]));
        int p1 = atomicAdd(&g_cursor[d.y], 1);
        g_cw[p1] = make_int2(s.y, __float_as_int(g_dinv[s.y]));
        int p2 = atomicAdd(&g_cursor[d.z], 1);
        g_cw[p2] = make_int2(s.z, __float_as_int(g_dinv[s.z]));
        int p3 = atomicAdd(&g_cursor[d.w], 1);
        g_cw[p3] = make_int2(s.w, __float_as_int(g_dinv[s.w]));
    }
    // reset state for the next graph replay
    if (i < N_NODES) g_deg[i] = 0;
    if (i == 0) g_alloc = 0;
}

// ---------------- prep: split W into fp16 hi/lo, [n][k] orientation ----------------
__global__ void k_prep_w(const float* __restrict__ W1, const float* __restrict__ W2) {
    int i = blockIdx.x * 256 + threadIdx.x;
    if (i < 128 * 128) {
        int k = i >> 7, n = i & 127;
        float v = W1[i];
        __half h = __float2half_rn(v);
        __half l = __float2half_rn(v - __half2float(h));
        g_w1hi[n * 128 + k] = h;
        g_w1lo[n * 128 + k] = l;
    } else if (i < 128 * 128 + 64 * 128) {
        int j = i - 128 * 128;
        int k = j >> 6, n = j & 63;
        float v = W2[j];
        __half h = __float2half_rn(v);
        __half l = __float2half_rn(v - __half2float(h));
        g_w2hi[n * 128 + k] = h;
        g_w2lo[n * 128 + k] = l;
    }
}

// ---------------- helpers ----------------
__device__ __forceinline__ void mma_f16(float& d0, float& d1, float& d2, float& d3,
                                        uint32_t a0, uint32_t a1, uint32_t a2, uint32_t a3,
                                        uint32_t b0, uint32_t b1) {
    asm volatile(
        "mma.sync.aligned.m16n8k16.row.col.f32.f16.f16.f32 "
        "{%0,%1,%2,%3}, {%4,%5,%6,%7}, {%8,%9}, {%0,%1,%2,%3};"
        : "+f"(d0), "+f"(d1), "+f"(d2), "+f"(d3)
        : "r"(a0), "r"(a1), "r"(a2), "r"(a3), "r"(b0), "r"(b1));
}
__device__ __forceinline__ uint32_t packh_hi2(float x, float y) {
    __half2 t = __halves2half2(__float2half_rn(x), __float2half_rn(y));
    return *(uint32_t*)&t;
}
__device__ __forceinline__ uint32_t packh_lo2(float x, float y) {
    __half hx = __float2half_rn(x), hy = __float2half_rn(y);
    __half2 t = __halves2half2(__float2half_rn(x - __half2float(hx)),
                               __float2half_rn(y - __half2float(hy)));
    return *(uint32_t*)&t;
}
__device__ __forceinline__ void fma_h8(float* acc, float w, uint4 rv) {
    float2 f0 = __half22float2(*(__half2*)&rv.x);
    float2 f1 = __half22float2(*(__half2*)&rv.y);
    float2 f2 = __half22float2(*(__half2*)&rv.z);
    float2 f3 = __half22float2(*(__half2*)&rv.w);
    acc[0] = fmaf(w, f0.x, acc[0]);
    acc[1] = fmaf(w, f0.y, acc[1]);
    acc[2] = fmaf(w, f1.x, acc[2]);
    acc[3] = fmaf(w, f1.y, acc[3]);
    acc[4] = fmaf(w, f2.x, acc[4]);
    acc[5] = fmaf(w, f2.y, acc[5]);
    acc[6] = fmaf(w, f3.x, acc[6]);
    acc[7] = fmaf(w, f3.y, acc[7]);
}

// ---------------- GEMM1: h1h = x @ W1, 3-term fp16 hi/lo (K split in 2 halves) ----------------
__global__ __launch_bounds__(256) void k_gemm1(const float* __restrict__ Ain) {
    extern __shared__ uint32_t smu[];
    constexpr int STRA = 36;
    constexpr int STRB = 68;

    uint32_t* As_hi = smu;
    uint32_t* As_lo = As_hi + 128 * STRA;
    uint32_t* Bs_hi = As_lo + 128 * STRA;
    uint32_t* Bs_lo = Bs_hi + 128 * STRB;

    const int tid = threadIdx.x;
    const int wid = tid >> 5;
    const int lane = tid & 31;
    const int g = lane >> 2;
    const int tg = lane & 3;
    const int row0 = blockIdx.x * 128;

    const uint32_t* WhG = (const uint32_t*)g_w1hi;
    const uint32_t* WlG = (const uint32_t*)g_w1lo;
    for (int i = tid; i < 128 * 64; i += 256) {
        int n = i >> 6, kp = i & 63;
        Bs_hi[n * STRB + kp] = WhG[i];
        Bs_lo[n * STRB + kp] = WlG[i];
    }

    const int wm = wid & 1;
    const int wn = wid >> 1;
    float d[4][4][4];
    #pragma unroll
    for (int mt = 0; mt < 4; mt++)
        #pragma unroll
        for (int nt = 0; nt < 4; nt++)
            #pragma unroll
            for (int j = 0; j < 4; j++) d[mt][nt][j] = 0.f;

    const float4* A4 = (const float4*)Ain;
    const uint32_t* Aterm[3] = {As_hi, As_hi, As_lo};
    const uint32_t* Bterm[3] = {Bs_hi, Bs_lo, Bs_hi};

    #pragma unroll
    for (int h = 0; h < 2; h++) {
        __syncthreads();
        #pragma unroll
        for (int t = 0; t < 8; t++) {
            int i = t * 256 + tid;
            int row = i >> 4, c4l = i & 15;
            int gr = row0 + row;
            float4 v = make_float4(0.f, 0.f, 0.f, 0.f);
            if (gr < N_NODES) v = A4[(size_t)gr * 32 + h * 16 + c4l];
            *(uint2*)&As_hi[row * STRA + c4l * 2] = make_uint2(packh_hi2(v.x, v.y), packh_hi2(v.z, v.w));
            *(uint2*)&As_lo[row * STRA + c4l * 2] = make_uint2(packh_lo2(v.x, v.y), packh_lo2(v.z, v.w));
        }
        __syncthreads();
        #pragma unroll
        for (int term = 0; term < 3; term++) {
            const uint32_t* Ab = Aterm[term] + (wm * 64 + g) * STRA;
            const uint32_t* Bb = Bterm[term] + (wn * 32 + g) * STRB;
            #pragma unroll
            for (int ks = 0; ks < 4; ks++) {
                int koA = ks * 8 + tg;
                int koB = (h * 4 + ks) * 8 + tg;
                uint32_t a[4][4], b[4][2];
                #pragma unroll
                for (int mt = 0; mt < 4; mt++) {
                    const uint32_t* Ar = Ab + mt * 16 * STRA;
                    a[mt][0] = Ar[koA];
                    a[mt][1] = Ar[8 * STRA + koA];
                    a[mt][2] = Ar[koA + 4];
                    a[mt][3] = Ar[8 * STRA + koA + 4];
                }
                #pragma unroll
                for (int nt = 0; nt < 4; nt++) {
                    const uint32_t* Br = Bb + nt * 8 * STRB;
                    b[nt][0] = Br[koB];
                    b[nt][1] = Br[koB + 4];
                }
                #pragma unroll
                for (int mt = 0; mt < 4; mt++)
                    #pragma unroll
                    for (int nt = 0; nt < 4; nt++)
                        mma_f16(d[mt][nt][0], d[mt][nt][1], d[mt][nt][2], d[mt][nt][3],
                                a[mt][0], a[mt][1], a[mt][2], a[mt][3],
                                b[nt][0], b[nt][1]);
            }
        }
    }

    #pragma unroll
    for (int mt = 0; mt < 4; mt++) {
        int r0 = row0 + wm * 64 + mt * 16 + g;
        #pragma unroll
        for (int nt = 0; nt < 4; nt++) {
            int c = wn * 32 + nt * 8 + tg * 2;
            if (r0 < N_NODES)
                *(__half2*)&g_h1h[(size_t)r0 * 128 + c] =
                    __floats2half2_rn(d[mt][nt][0], d[mt][nt][1]);
            if (r0 + 8 < N_NODES)
                *(__half2*)&g_h1h[(size_t)(r0 + 8) * 128 + c] =
                    __floats2half2_rn(d[mt][nt][2], d[mt][nt][3]);
        }
    }
}

// ---------------- GEMM2: h2h = a1h @ W2, 2-term (A fp16 exact; B fp16 hi/lo) ----------------
__global__ __launch_bounds__(256) void k_gemm2(int tile0) {
    extern __shared__ uint32_t smu[];
    constexpr int STRA = 36;
    constexpr int STRB = 68;

    uint32_t* As    = smu;
    uint32_t* Bs_hi = As + 128 * STRA;
    uint32_t* Bs_lo = Bs_hi + 64 * STRB;

    const int tid = threadIdx.x;
    const int wid = tid >> 5;
    const int lane = tid & 31;
    const int g = lane >> 2;
    const int tg = lane & 3;
    const int row0 = (tile0 + blockIdx.x) * 128;

    const uint32_t* WhG = (const uint32_t*)g_w2hi;
    const uint32_t* WlG = (const uint32_t*)g_w2lo;
    for (int i = tid; i < 64 * 64; i += 256) {
        int n = i >> 6, kp = i & 63;
        Bs_hi[n * STRB + kp] = WhG[i];
        Bs_lo[n * STRB + kp] = WlG[i];
    }

    const int wm = wid & 3;
    const int wn = wid >> 2;
    float d[2][4][4];
    #pragma unroll
    for (int mt = 0; mt < 2; mt++)
        #pragma unroll
        for (int nt = 0; nt < 4; nt++)
            #pragma unroll
            for (int j = 0; j < 4; j++) d[mt][nt][j] = 0.f;

    const uint2* A2h = (const uint2*)g_a1h;
    const uint32_t* Bterm[2] = {Bs_hi, Bs_lo};

    #pragma unroll
    for (int h = 0; h < 2; h++) {
        __syncthreads();
        #pragma unroll
        for (int t = 0; t < 8; t++) {
            int i = t * 256 + tid;
            int row = i >> 4, c4l = i & 15;
            int gr = row0 + row;
            uint2 v = make_uint2(0u, 0u);
            if (gr < N_NODES) v = A2h[(size_t)gr * 32 + h * 16 + c4l];
            *(uint2*)&As[row * STRA + c4l * 2] = v;
        }
        __syncthreads();
        #pragma unroll
        for (int term = 0; term < 2; term++) {
            const uint32_t* Ab = As + (wm * 32 + g) * STRA;
            const uint32_t* Bb = Bterm[term] + (wn * 32 + g) * STRB;
            #pragma unroll
            for (int ks = 0; ks < 4; ks++) {
                int koA = ks * 8 + tg;
                int koB = (h * 4 + ks) * 8 + tg;
                uint32_t a[2][4], b[4][2];
                #pragma unroll
                for (int mt = 0; mt < 2; mt++) {
                    const uint32_t* Ar = Ab + mt * 16 * STRA;
                    a[mt][0] = Ar[koA];
                    a[mt][1] = Ar[8 * STRA + koA];
                    a[mt][2] = Ar[koA + 4];
                    a[mt][3] = Ar[8 * STRA + koA + 4];
                }
                #pragma unroll
                for (int nt = 0; nt < 4; nt++) {
                    const uint32_t* Br = Bb + nt * 8 * STRB;
                    b[nt][0] = Br[koB];
                    b[nt][1] = Br[koB + 4];
                }
                #pragma unroll
                for (int mt = 0; mt < 2; mt++)
                    #pragma unroll
                    for (int nt = 0; nt < 4; nt++)
                        mma_f16(d[mt][nt][0], d[mt][nt][1], d[mt][nt][2], d[mt][nt][3],
                                a[mt][0], a[mt][1], a[mt][2], a[mt][3],
                                b[nt][0], b[nt][1]);
            }
        }
    }

    #pragma unroll
    for (int mt = 0; mt < 2; mt++) {
        int r0 = row0 + wm * 32 + mt * 16 + g;
        #pragma unroll
        for (int nt = 0; nt < 4; nt++) {
            int c = wn * 32 + nt * 8 + tg * 2;
            if (r0 < N_NODES)
                *(__half2*)&g_h2h[(size_t)r0 * 64 + c] =
                    __floats2half2_rn(d[mt][nt][0], d[mt][nt][1]);
            if (r0 + 8 < N_NODES)
                *(__half2*)&g_h2h[(size_t)(r0 + 8) * 64 + c] =
                    __floats2half2_rn(d[mt][nt][2], d[mt][nt][3]);
        }
    }
}

// ---------------- agg1: half-warp per node (16 lanes x uint4 = 256B row) ----------------
__global__ __launch_bounds__(256) void k_agg1(const float* __restrict__ b1,
                                              int node0, int node1) {
    int node = node0 + blockIdx.x * 16 + (threadIdx.x >> 4);
    if (node >= node1) return;
    int hl = threadIdx.x & 15;
    float di = g_dinv[node];
    const uint4* H = (const uint4*)g_h1h;
    float acc[8] = {0.f, 0.f, 0.f, 0.f, 0.f, 0.f, 0.f, 0.f};
    uint4 sv = __ldg(&H[(size_t)node * 16 + hl]);
    fma_h8(acc, di, sv);
    int2 seg = __ldg(&g_seg[node]);
    #pragma unroll 4
    for (int e = seg.x; e < seg.y; e++) {
        int2 cw = __ldg(&g_cw[e]);
        float w = __int_as_float(cw.y);
        uint4 hv = __ldg(&H[(size_t)cw.x * 16 + hl]);
        fma_h8(acc, w, hv);
    }
    float4 bv0 = ((const float4*)b1)[hl * 2];
    float4 bv1 = ((const float4*)b1)[hl * 2 + 1];
    float o0 = fmaxf(fmaf(acc[0], di, bv0.x), 0.f);
    float o1 = fmaxf(fmaf(acc[1], di, bv0.y), 0.f);
    float o2 = fmaxf(fmaf(acc[2], di, bv0.z), 0.f);
    float o3 = fmaxf(fmaf(acc[3], di, bv0.w), 0.f);
    float o4 = fmaxf(fmaf(acc[4], di, bv1.x), 0.f);
    float o5 = fmaxf(fmaf(acc[5], di, bv1.y), 0.f);
    float o6 = fmaxf(fmaf(acc[6], di, bv1.z), 0.f);
    float o7 = fmaxf(fmaf(acc[7], di, bv1.w), 0.f);
    uint4 packed;
    *(__half2*)&packed.x = __floats2half2_rn(o0, o1);
    *(__half2*)&packed.y = __floats2half2_rn(o2, o3);
    *(__half2*)&packed.z = __floats2half2_rn(o4, o5);
    *(__half2*)&packed.w = __floats2half2_rn(o6, o7);
    ((uint4*)g_a1h)[(size_t)node * 16 + hl] = packed;
}

// ---------------- agg2: quarter-warp per node (8 lanes x uint4 = 128B row) ----------------
__global__ __launch_bounds__(256) void k_agg2(const float* __restrict__ b2,
                                              float* __restrict__ out) {
    int node = blockIdx.x * 32 + (threadIdx.x >> 3);   // 3125*32 = 100000
    int ql = threadIdx.x & 7;
    float di = g_dinv[node];
    const uint4* H = (const uint4*)g_h2h;
    float acc[8] = {0.f, 0.f, 0.f, 0.f, 0.f, 0.f, 0.f, 0.f};
    uint4 sv = __ldg(&H[(size_t)node * 8 + ql]);
    fma_h8(acc, di, sv);
    int2 seg = __ldg(&g_seg[node]);
    #pragma unroll 4
    for (int e = seg.x; e < seg.y; e++) {
        int2 cw = __ldg(&g_cw[e]);
        float w = __int_as_float(cw.y);
        uint4 hv = __ldg(&H[(size_t)cw.x * 8 + ql]);
        fma_h8(acc, w, hv);
    }
    float4 bv0 = ((const float4*)b2)[ql * 2];
    float4 bv1 = ((const float4*)b2)[ql * 2 + 1];
    float v[8];
    v[0] = fmaf(acc[0], di, bv0.x);
    v[1] = fmaf(acc[1], di, bv0.y);
    v[2] = fmaf(acc[2], di, bv0.z);
    v[3] = fmaf(acc[3], di, bv0.w);
    v[4] = fmaf(acc[4], di, bv1.x);
    v[5] = fmaf(acc[5], di, bv1.y);
    v[6] = fmaf(acc[6], di, bv1.z);
    v[7] = fmaf(acc[7], di, bv1.w);

    float m = v[0];
    #pragma unroll
    for (int j = 1; j < 8; j++) m = fmaxf(m, v[j]);
    #pragma unroll
    for (int o = 4; o > 0; o >>= 1) m = fmaxf(m, __shfl_xor_sync(0xffffffffu, m, o));
    float s = 0.f;
    #pragma unroll
    for (int j = 0; j < 8; j++) s += expf(v[j] - m);
    #pragma unroll
    for (int o = 4; o > 0; o >>= 1) s += __shfl_xor_sync(0xffffffffu, s, o);
    float lse = m + logf(s);
    ((float4*)out)[(size_t)node * 16 + ql * 2] =
        make_float4(v[0] - lse, v[1] - lse, v[2] - lse, v[3] - lse);
    ((float4*)out)[(size_t)node * 16 + ql * 2 + 1] =
        make_float4(v[4] - lse, v[5] - lse, v[6] - lse, v[7] - lse);
}

// ---------------- launch ----------------
extern "C" void kernel_launch(void* const* d_in, const int* in_sizes, int n_in,
                              void* d_out, int out_size) {
    const float* x  = (const float*)d_in[0];
    const int*   ei = (const int*)d_in[1];
    const float* W1 = (const float*)d_in[2];
    const float* b1 = (const float*)d_in[3];
    const float* W2 = (const float*)d_in[4];
    const float* b2 = (const float*)d_in[5];
    float* out = (float*)d_out;

    const int4* src4 = (const int4*)ei;
    const int4* dst4 = (const int4*)(ei + N_EDGES);

    const int SMEM1 = (2 * 128 * 36 + 2 * 128 * 68) * 4;  // 106496
    const int SMEM2 = (128 * 36 + 2 * 64 * 68) * 4;       //  53248
    cudaFuncSetAttribute(k_gemm1, cudaFuncAttributeMaxDynamicSharedMemorySize, SMEM1);
    cudaFuncSetAttribute(k_gemm2, cudaFuncAttributeMaxDynamicSharedMemorySize, SMEM2);

    cudaStream_t s1;
    cudaStreamCreateWithFlags(&s1, cudaStreamNonBlocking);
    cudaEvent_t evFork, evG1, evG2;
    cudaEvent_t evA[CHUNKS];
    cudaEventCreateWithFlags(&evFork, cudaEventDisableTiming);
    cudaEventCreateWithFlags(&evG1, cudaEventDisableTiming);
    cudaEventCreateWithFlags(&evG2, cudaEventDisableTiming);
    for (int c = 0; c < CHUNKS; c++) cudaEventCreateWithFlags(&evA[c], cudaEventDisableTiming);

    cudaEventRecord(evFork, 0);
    cudaStreamWaitEvent(s1, evFork, 0);

    // side stream: weight prep + GEMM1
    k_prep_w<<<(128 * 128 + 64 * 128 + 255) / 256, 256, 0, s1>>>(W1, W2);
    k_gemm1<<<NTILES, 256, SMEM1, s1>>>(x);
    cudaEventRecord(evG1, s1);

    // main stream: CSR build (count, single-pass scan, fill)
    k_count<<<(N_EDGES / 4 + 255) / 256, 256>>>(dst4);
    k_scan_alloc<<<(N_NODES + 511) / 512, 512>>>();
    k_fill<<<(N_EDGES / 4 + 255) / 256, 256>>>(src4, dst4);

    cudaStreamWaitEvent(0, evG1, 0);

    // pipelined agg1 (main) -> gemm2 chunk (side); descending chunks shrink the tail
    const int chunkTiles[CHUNKS] = {250, 250, 200, 82};
    int t0 = 0;
    for (int c = 0; c < CHUNKS; c++) {
        int t1 = t0 + chunkTiles[c];
        int n0 = t0 * 128;
        int n1 = (t1 * 128 < N_NODES) ? t1 * 128 : N_NODES;
        int blocks = (n1 - n0 + 15) / 16;
        k_agg1<<<blocks, 256>>>(b1, n0, n1);
        cudaEventRecord(evA[c], 0);
        cudaStreamWaitEvent(s1, evA[c], 0);
        k_gemm2<<<t1 - t0, 256, SMEM2, s1>>>(t0);
        t0 = t1;
    }
    cudaEventRecord(evG2, s1);
    cudaStreamWaitEvent(0, evG2, 0);

    k_agg2<<<N_NODES / 32, 256>>>(b2, out);
}

// round 16
// speedup vs baseline: 1.1795x; 1.0195x over previous
#include <cuda_runtime.h>
#include <cuda_bf16.h>
#include <cuda_fp16.h>
#include <cstdint>
#include <math.h>

#define N_NODES 100000
#define N_EDGES 1600000
#define NTILES 782           // ceil(100000/128)
#define CHUNKS 4

// ---------------- scratch ----------------
__device__ int   g_deg[N_NODES];        // zeroed by k_fill tail each run (zero-init at load)
__device__ int   g_alloc;               // arrival-order segment allocator (zeroed by k_fill tail)
__device__ float g_dinv[N_NODES];
__device__ int2  g_seg[N_NODES];        // (beg, end) of each node's edge segment
__device__ int   g_cursor[N_NODES];
__device__ int2  g_cw[N_EDGES];
__device__ __align__(16) __half g_h1h[(size_t)N_NODES * 128];
__device__ __align__(16) __half g_a1h[(size_t)N_NODES * 128];
__device__ __align__(16) __half g_h2h[(size_t)N_NODES * 64];
__device__ __align__(16) __half g_w1hi[128 * 128];
__device__ __align__(16) __half g_w1lo[128 * 128];
__device__ __align__(16) __half g_w2h[64 * 128];

// ---------------- degree / scan / CSR ----------------
__global__ void k_count(const int4* __restrict__ dst4) {
    int i = blockIdx.x * 256 + threadIdx.x;
    if (i < N_EDGES / 4) {
        int4 d = __ldg(&dst4[i]);
        atomicAdd(&g_deg[d.x], 1);
        atomicAdd(&g_deg[d.y], 1);
        atomicAdd(&g_deg[d.z], 1);
        atomicAdd(&g_deg[d.w], 1);
    }
}

// single-pass scan: block-local prefix + ONE atomicAdd for the block offset
__global__ void k_scan_alloc() {
    __shared__ int wsum[16];
    __shared__ int s_base;
    int tid = threadIdx.x;
    int lane = tid & 31, wid = tid >> 5;
    int i = blockIdx.x * 512 + tid;
    int c = 0;
    if (i < N_NODES) {
        int d = g_deg[i];
        g_dinv[i] = rsqrtf((float)(d + 1));
        c = d;
    }
    int v = c;
    #pragma unroll
    for (int o = 1; o < 32; o <<= 1) {
        int t = __shfl_up_sync(0xffffffffu, v, o);
        if (lane >= o) v += t;
    }
    if (lane == 31) wsum[wid] = v;
    __syncthreads();
    if (wid == 0) {
        int s = (lane < 16) ? wsum[lane] : 0;
        #pragma unroll
        for (int o = 1; o < 16; o <<= 1) {
            int t = __shfl_up_sync(0xffffffffu, s, o);
            if (lane >= o) s += t;
        }
        if (lane < 16) wsum[lane] = s;
    }
    __syncthreads();
    if (tid == 0) s_base = atomicAdd(&g_alloc, wsum[15]);
    __syncthreads();
    int off = (wid > 0) ? wsum[wid - 1] : 0;
    if (i < N_NODES) {
        int beg = s_base + off + v - c;
        g_seg[i] = make_int2(beg, beg + c);
        g_cursor[i] = beg;
    }
}

__global__ void k_fill(const int4* __restrict__ src4, const int4* __restrict__ dst4) {
    int i = blockIdx.x * 256 + threadIdx.x;
    if (i < N_EDGES / 4) {
        int4 s = __ldg(&src4[i]);
        int4 d = __ldg(&dst4[i]);
        int p0 = atomicAdd(&g_cursor[d.x], 1);
        g_cw[p0] = make_int2(s.x, __float_as_int(g_dinv[s.x]));
        int p1 = atomicAdd(&g_cursor[d.y], 1);
        g_cw[p1] = make_int2(s.y, __float_as_int(g_dinv[s.y]));
        int p2 = atomicAdd(&g_cursor[d.z], 1);
        g_cw[p2] = make_int2(s.z, __float_as_int(g_dinv[s.z]));
        int p3 = atomicAdd(&g_cursor[d.w], 1);
        g_cw[p3] = make_int2(s.w, __float_as_int(g_dinv[s.w]));
    }
    // reset state for the next graph replay
    if (i < N_NODES) g_deg[i] = 0;
    if (i == 0) g_alloc = 0;
}

// ---------------- prep: W1 fp16 hi/lo, W2 fp16; [n][k] orientation ----------------
__global__ void k_prep_w(const float* __restrict__ W1, const float* __restrict__ W2) {
    int i = blockIdx.x * 256 + threadIdx.x;
    if (i < 128 * 128) {
        int k = i >> 7, n = i & 127;
        float v = W1[i];
        __half h = __float2half_rn(v);
        __half l = __float2half_rn(v - __half2float(h));
        g_w1hi[n * 128 + k] = h;
        g_w1lo[n * 128 + k] = l;
    } else if (i < 128 * 128 + 64 * 128) {
        int j = i - 128 * 128;
        int k = j >> 6, n = j & 63;
        g_w2h[n * 128 + k] = __float2half_rn(W2[j]);
    }
}

// ---------------- helpers ----------------
__device__ __forceinline__ void mma_f16(float& d0, float& d1, float& d2, float& d3,
                                        uint32_t a0, uint32_t a1, uint32_t a2, uint32_t a3,
                                        uint32_t b0, uint32_t b1) {
    asm volatile(
        "mma.sync.aligned.m16n8k16.row.col.f32.f16.f16.f32 "
        "{%0,%1,%2,%3}, {%4,%5,%6,%7}, {%8,%9}, {%0,%1,%2,%3};"
        : "+f"(d0), "+f"(d1), "+f"(d2), "+f"(d3)
        : "r"(a0), "r"(a1), "r"(a2), "r"(a3), "r"(b0), "r"(b1));
}
__device__ __forceinline__ uint32_t packh_hi2(float x, float y) {
    __half2 t = __halves2half2(__float2half_rn(x), __float2half_rn(y));
    return *(uint32_t*)&t;
}
__device__ __forceinline__ void fma_h8(float* acc, float w, uint4 rv) {
    float2 f0 = __half22float2(*(__half2*)&rv.x);
    float2 f1 = __half22float2(*(__half2*)&rv.y);
    float2 f2 = __half22float2(*(__half2*)&rv.z);
    float2 f3 = __half22float2(*(__half2*)&rv.w);
    acc[0] = fmaf(w, f0.x, acc[0]);
    acc[1] = fmaf(w, f0.y, acc[1]);
    acc[2] = fmaf(w, f1.x, acc[2]);
    acc[3] = fmaf(w, f1.y, acc[3]);
    acc[4] = fmaf(w, f2.x, acc[4]);
    acc[5] = fmaf(w, f2.y, acc[5]);
    acc[6] = fmaf(w, f3.x, acc[6]);
    acc[7] = fmaf(w, f3.y, acc[7]);
}

// ---------------- GEMM1: h1h = x @ W1, 2-term (A fp16; B fp16 hi/lo) ----------------
__global__ __launch_bounds__(256) void k_gemm1(const float* __restrict__ Ain) {
    extern __shared__ uint32_t smu[];
    constexpr int STRA = 36;
    constexpr int STRB = 68;

    uint32_t* As    = smu;                  // 128*36
    uint32_t* Bs_hi = As + 128 * STRA;      // 128*68
    uint32_t* Bs_lo = Bs_hi + 128 * STRB;

    const int tid = threadIdx.x;
    const int wid = tid >> 5;
    const int lane = tid & 31;
    const int g = lane >> 2;
    const int tg = lane & 3;
    const int row0 = blockIdx.x * 128;

    const uint32_t* WhG = (const uint32_t*)g_w1hi;
    const uint32_t* WlG = (const uint32_t*)g_w1lo;
    for (int i = tid; i < 128 * 64; i += 256) {
        int n = i >> 6, kp = i & 63;
        Bs_hi[n * STRB + kp] = WhG[i];
        Bs_lo[n * STRB + kp] = WlG[i];
    }

    const int wm = wid & 1;
    const int wn = wid >> 1;
    float d[4][4][4];
    #pragma unroll
    for (int mt = 0; mt < 4; mt++)
        #pragma unroll
        for (int nt = 0; nt < 4; nt++)
            #pragma unroll
            for (int j = 0; j < 4; j++) d[mt][nt][j] = 0.f;

    const float4* A4 = (const float4*)Ain;
    const uint32_t* Bterm[2] = {Bs_hi, Bs_lo};

    #pragma unroll
    for (int h = 0; h < 2; h++) {
        __syncthreads();
        #pragma unroll
        for (int t = 0; t < 8; t++) {
            int i = t * 256 + tid;
            int row = i >> 4, c4l = i & 15;
            int gr = row0 + row;
            float4 v = make_float4(0.f, 0.f, 0.f, 0.f);
            if (gr < N_NODES) v = A4[(size_t)gr * 32 + h * 16 + c4l];
            *(uint2*)&As[row * STRA + c4l * 2] = make_uint2(packh_hi2(v.x, v.y), packh_hi2(v.z, v.w));
        }
        __syncthreads();
        #pragma unroll
        for (int term = 0; term < 2; term++) {
            const uint32_t* Ab = As + (wm * 64 + g) * STRA;
            const uint32_t* Bb = Bterm[term] + (wn * 32 + g) * STRB;
            #pragma unroll
            for (int ks = 0; ks < 4; ks++) {
                int koA = ks * 8 + tg;
                int koB = (h * 4 + ks) * 8 + tg;
                uint32_t a[4][4], b[4][2];
                #pragma unroll
                for (int mt = 0; mt < 4; mt++) {
                    const uint32_t* Ar = Ab + mt * 16 * STRA;
                    a[mt][0] = Ar[koA];
                    a[mt][1] = Ar[8 * STRA + koA];
                    a[mt][2] = Ar[koA + 4];
                    a[mt][3] = Ar[8 * STRA + koA + 4];
                }
                #pragma unroll
                for (int nt = 0; nt < 4; nt++) {
                    const uint32_t* Br = Bb + nt * 8 * STRB;
                    b[nt][0] = Br[koB];
                    b[nt][1] = Br[koB + 4];
                }
                #pragma unroll
                for (int mt = 0; mt < 4; mt++)
                    #pragma unroll
                    for (int nt = 0; nt < 4; nt++)
                        mma_f16(d[mt][nt][0], d[mt][nt][1], d[mt][nt][2], d[mt][nt][3],
                                a[mt][0], a[mt][1], a[mt][2], a[mt][3],
                                b[nt][0], b[nt][1]);
            }
        }
    }

    #pragma unroll
    for (int mt = 0; mt < 4; mt++) {
        int r0 = row0 + wm * 64 + mt * 16 + g;
        #pragma unroll
        for (int nt = 0; nt < 4; nt++) {
            int c = wn * 32 + nt * 8 + tg * 2;
            if (r0 < N_NODES)
                *(__half2*)&g_h1h[(size_t)r0 * 128 + c] =
                    __floats2half2_rn(d[mt][nt][0], d[mt][nt][1]);
            if (r0 + 8 < N_NODES)
                *(__half2*)&g_h1h[(size_t)(r0 + 8) * 128 + c] =
                    __floats2half2_rn(d[mt][nt][2], d[mt][nt][3]);
        }
    }
}

// ---------------- GEMM2: h2h = a1h @ W2, 1-term pure fp16 ----------------
__global__ __launch_bounds__(256) void k_gemm2(int tile0) {
    extern __shared__ uint32_t smu[];
    constexpr int STRA = 36;
    constexpr int STRB = 68;

    uint32_t* As = smu;               // 128*36
    uint32_t* Bs = As + 128 * STRA;   // 64*68

    const int tid = threadIdx.x;
    const int wid = tid >> 5;
    const int lane = tid & 31;
    const int g = lane >> 2;
    const int tg = lane & 3;
    const int row0 = (tile0 + blockIdx.x) * 128;

    const uint32_t* WG = (const uint32_t*)g_w2h;
    for (int i = tid; i < 64 * 64; i += 256) {
        int n = i >> 6, kp = i & 63;
        Bs[n * STRB + kp] = WG[i];
    }

    const int wm = wid & 3;
    const int wn = wid >> 2;
    float d[2][4][4];
    #pragma unroll
    for (int mt = 0; mt < 2; mt++)
        #pragma unroll
        for (int nt = 0; nt < 4; nt++)
            #pragma unroll
            for (int j = 0; j < 4; j++) d[mt][nt][j] = 0.f;

    const uint2* A2h = (const uint2*)g_a1h;

    #pragma unroll
    for (int h = 0; h < 2; h++) {
        __syncthreads();
        #pragma unroll
        for (int t = 0; t < 8; t++) {
            int i = t * 256 + tid;
            int row = i >> 4, c4l = i & 15;
            int gr = row0 + row;
            uint2 v = make_uint2(0u, 0u);
            if (gr < N_NODES) v = A2h[(size_t)gr * 32 + h * 16 + c4l];
            *(uint2*)&As[row * STRA + c4l * 2] = v;
        }
        __syncthreads();
        const uint32_t* Ab = As + (wm * 32 + g) * STRA;
        const uint32_t* Bb = Bs + (wn * 32 + g) * STRB;
        #pragma unroll
        for (int ks = 0; ks < 4; ks++) {
            int koA = ks * 8 + tg;
            int koB = (h * 4 + ks) * 8 + tg;
            uint32_t a[2][4], b[4][2];
            #pragma unroll
            for (int mt = 0; mt < 2; mt++) {
                const uint32_t* Ar = Ab + mt * 16 * STRA;
                a[mt][0] = Ar[koA];
                a[mt][1] = Ar[8 * STRA + koA];
                a[mt][2] = Ar[koA + 4];
                a[mt][3] = Ar[8 * STRA + koA + 4];
            }
            #pragma unroll
            for (int nt = 0; nt < 4; nt++) {
                const uint32_t* Br = Bb + nt * 8 * STRB;
                b[nt][0] = Br[koB];
                b[nt][1] = Br[koB + 4];
            }
            #pragma unroll
            for (int mt = 0; mt < 2; mt++)
                #pragma unroll
                for (int nt = 0; nt < 4; nt++)
                    mma_f16(d[mt][nt][0], d[mt][nt][1], d[mt][nt][2], d[mt][nt][3],
                            a[mt][0], a[mt][1], a[mt][2], a[mt][3],
                            b[nt][0], b[nt][1]);
        }
    }

    #pragma unroll
    for (int mt = 0; mt < 2; mt++) {
        int r0 = row0 + wm * 32 + mt * 16 + g;
        #pragma unroll
        for (int nt = 0; nt < 4; nt++) {
            int c = wn * 32 + nt * 8 + tg * 2;
            if (r0 < N_NODES)
                *(__half2*)&g_h2h[(size_t)r0 * 64 + c] =
                    __floats2half2_rn(d[mt][nt][0], d[mt][nt][1]);
            if (r0 + 8 < N_NODES)
                *(__half2*)&g_h2h[(size_t)(r0 + 8) * 64 + c] =
                    __floats2half2_rn(d[mt][nt][2], d[mt][nt][3]);
        }
    }
}

// ---------------- agg1: half-warp per node (16 lanes x uint4 = 256B row) ----------------
__global__ __launch_bounds__(256) void k_agg1(const float* __restrict__ b1,
                                              int node0, int node1) {
    int node = node0 + blockIdx.x * 16 + (threadIdx.x >> 4);
    if (node >= node1) return;
    int hl = threadIdx.x & 15;
    float di = g_dinv[node];
    const uint4* H = (const uint4*)g_h1h;
    float acc[8] = {0.f, 0.f, 0.f, 0.f, 0.f, 0.f, 0.f, 0.f};
    uint4 sv = __ldg(&H[(size_t)node * 16 + hl]);
    fma_h8(acc, di, sv);
    int2 seg = __ldg(&g_seg[node]);
    #pragma unroll 4
    for (int e = seg.x; e < seg.y; e++) {
        int2 cw = __ldg(&g_cw[e]);
        float w = __int_as_float(cw.y);
        uint4 hv = __ldg(&H[(size_t)cw.x * 16 + hl]);
        fma_h8(acc, w, hv);
    }
    float4 bv0 = ((const float4*)b1)[hl * 2];
    float4 bv1 = ((const float4*)b1)[hl * 2 + 1];
    float o0 = fmaxf(fmaf(acc[0], di, bv0.x), 0.f);
    float o1 = fmaxf(fmaf(acc[1], di, bv0.y), 0.f);
    float o2 = fmaxf(fmaf(acc[2], di, bv0.z), 0.f);
    float o3 = fmaxf(fmaf(acc[3], di, bv0.w), 0.f);
    float o4 = fmaxf(fmaf(acc[4], di, bv1.x), 0.f);
    float o5 = fmaxf(fmaf(acc[5], di, bv1.y), 0.f);
    float o6 = fmaxf(fmaf(acc[6], di, bv1.z), 0.f);
    float o7 = fmaxf(fmaf(acc[7], di, bv1.w), 0.f);
    uint4 packed;
    *(__half2*)&packed.x = __floats2half2_rn(o0, o1);
    *(__half2*)&packed.y = __floats2half2_rn(o2, o3);
    *(__half2*)&packed.z = __floats2half2_rn(o4, o5);
    *(__half2*)&packed.w = __floats2half2_rn(o6, o7);
    ((uint4*)g_a1h)[(size_t)node * 16 + hl] = packed;
}

// ---------------- agg2: quarter-warp per node (8 lanes x uint4 = 128B row) ----------------
__global__ __launch_bounds__(256) void k_agg2(const float* __restrict__ b2,
                                              float* __restrict__ out) {
    int node = blockIdx.x * 32 + (threadIdx.x >> 3);   // 3125*32 = 100000
    int ql = threadIdx.x & 7;
    float di = g_dinv[node];
    const uint4* H = (const uint4*)g_h2h;
    float acc[8] = {0.f, 0.f, 0.f, 0.f, 0.f, 0.f, 0.f, 0.f};
    uint4 sv = __ldg(&H[(size_t)node * 8 + ql]);
    fma_h8(acc, di, sv);
    int2 seg = __ldg(&g_seg[node]);
    #pragma unroll 4
    for (int e = seg.x; e < seg.y; e++) {
        int2 cw = __ldg(&g_cw[e]);
        float w = __int_as_float(cw.y);
        uint4 hv = __ldg(&H[(size_t)cw.x * 8 + ql]);
        fma_h8(acc, w, hv);
    }
    float4 bv0 = ((const float4*)b2)[ql * 2];
    float4 bv1 = ((const float4*)b2)[ql * 2 + 1];
    float v[8];
    v[0] = fmaf(acc[0], di, bv0.x);
    v[1] = fmaf(acc[1], di, bv0.y);
    v[2] = fmaf(acc[2], di, bv0.z);
    v[3] = fmaf(acc[3], di, bv0.w);
    v[4] = fmaf(acc[4], di, bv1.x);
    v[5] = fmaf(acc[5], di, bv1.y);
    v[6] = fmaf(acc[6], di, bv1.z);
    v[7] = fmaf(acc[7], di, bv1.w);

    float m = v[0];
    #pragma unroll
    for (int j = 1; j < 8; j++) m = fmaxf(m, v[j]);
    #pragma unroll
    for (int o = 4; o > 0; o >>= 1) m = fmaxf(m, __shfl_xor_sync(0xffffffffu, m, o));
    float s = 0.f;
    #pragma unroll
    for (int j = 0; j < 8; j++) s += expf(v[j] - m);
    #pragma unroll
    for (int o = 4; o > 0; o >>= 1) s += __shfl_xor_sync(0xffffffffu, s, o);
    float lse = m + logf(s);
    ((float4*)out)[(size_t)node * 16 + ql * 2] =
        make_float4(v[0] - lse, v[1] - lse, v[2] - lse, v[3] - lse);
    ((float4*)out)[(size_t)node * 16 + ql * 2 + 1] =
        make_float4(v[4] - lse, v[5] - lse, v[6] - lse, v[7] - lse);
}

// ---------------- launch ----------------
extern "C" void kernel_launch(void* const* d_in, const int* in_sizes, int n_in,
                              void* d_out, int out_size) {
    const float* x  = (const float*)d_in[0];
    const int*   ei = (const int*)d_in[1];
    const float* W1 = (const float*)d_in[2];
    const float* b1 = (const float*)d_in[3];
    const float* W2 = (const float*)d_in[4];
    const float* b2 = (const float*)d_in[5];
    float* out = (float*)d_out;

    const int4* src4 = (const int4*)ei;
    const int4* dst4 = (const int4*)(ei + N_EDGES);

    const int SMEM1 = (128 * 36 + 2 * 128 * 68) * 4;  // 88064 -> 2 blocks/SM
    const int SMEM2 = (128 * 36 + 64 * 68) * 4;       // 35840 -> 6 blocks/SM
    cudaFuncSetAttribute(k_gemm1, cudaFuncAttributeMaxDynamicSharedMemorySize, SMEM1);
    cudaFuncSetAttribute(k_gemm2, cudaFuncAttributeMaxDynamicSharedMemorySize, SMEM2);

    cudaStream_t s1;
    cudaStreamCreateWithFlags(&s1, cudaStreamNonBlocking);
    cudaEvent_t evFork, evG1, evG2;
    cudaEvent_t evA[CHUNKS];
    cudaEventCreateWithFlags(&evFork, cudaEventDisableTiming);
    cudaEventCreateWithFlags(&evG1, cudaEventDisableTiming);
    cudaEventCreateWithFlags(&evG2, cudaEventDisableTiming);
    for (int c = 0; c < CHUNKS; c++) cudaEventCreateWithFlags(&evA[c], cudaEventDisableTiming);

    cudaEventRecord(evFork, 0);
    cudaStreamWaitEvent(s1, evFork, 0);

    // side stream: weight prep + GEMM1
    k_prep_w<<<(128 * 128 + 64 * 128 + 255) / 256, 256, 0, s1>>>(W1, W2);
    k_gemm1<<<NTILES, 256, SMEM1, s1>>>(x);
    cudaEventRecord(evG1, s1);

    // main stream: CSR build (count, single-pass scan, fill)
    k_count<<<(N_EDGES / 4 + 255) / 256, 256>>>(dst4);
    k_scan_alloc<<<(N_NODES + 511) / 512, 512>>>();
    k_fill<<<(N_EDGES / 4 + 255) / 256, 256>>>(src4, dst4);

    cudaStreamWaitEvent(0, evG1, 0);

    // pipelined agg1 (main) -> gemm2 chunk (side); descending chunks shrink the tail
    const int chunkTiles[CHUNKS] = {250, 250, 200, 82};
    int t0 = 0;
    for (int c = 0; c < CHUNKS; c++) {
        int t1 = t0 + chunkTiles[c];
        int n0 = t0 * 128;
        int n1 = (t1 * 128 < N_NODES) ? t1 * 128 : N_NODES;
        int blocks = (n1 - n0 + 15) / 16;
        k_agg1<<<blocks, 256>>>(b1, n0, n1);
        cudaEventRecord(evA[c], 0);
        cudaStreamWaitEvent(s1, evA[c], 0);
        k_gemm2<<<t1 - t0, 256, SMEM2, s1>>>(t0);
        t0 = t1;
    }
    cudaEventRecord(evG2, s1);
    cudaStreamWaitEvent(0, evG2, 0);

    k_agg2<<<N_NODES / 32, 256>>>(b2, out);
}